// round 1
// baseline (speedup 1.0000x reference)
#include <cuda_runtime.h>
#include <math_constants.h>

// Problem constants: B=4, H=64, W=64, C=64, GROUPS=8
#define BATCH 4
#define HDIM 64
#define WDIM 64
#define CDIM 64
#define GROUPS 8
#define SEQ (HDIM * WDIM)          // 4096 tokens per batch
#define NTOK (BATCH * SEQ)         // 16384
#define GN_EPS 1e-5f
#define SCALE 0.125f               // C^-0.5

// ---------------- scratch (device globals; no allocation allowed) ----------
__device__ float g_mean[BATCH * GROUPS];
__device__ float g_rstd[BATCH * GROUPS];
__device__ float g_xn[NTOK * CDIM];          // xn, token-major [b][t][c]
__device__ float g_qT[BATCH * CDIM * SEQ];   // Q transposed   [b][c][t]
__device__ float g_kT[BATCH * CDIM * SEQ];   // K transposed   [b][c][t]
__device__ float g_v [NTOK * CDIM];          // V token-major  [b][t][c]

// ---------------- kernel 1: group-norm statistics --------------------------
// One block per (b,g). Group = x[b, 8g:8g+8, :, :] -> contiguous 32768 floats.
__global__ void gn_stats_kernel(const float* __restrict__ x) {
    int bg = blockIdx.x;                       // 0..31
    const float4* p = (const float4*)(x + (size_t)bg * 32768);
    float s = 0.f, s2 = 0.f;
    for (int i = threadIdx.x; i < 8192; i += 256) {
        float4 v = p[i];
        s  += v.x + v.y + v.z + v.w;
        s2 += v.x * v.x + v.y * v.y + v.z * v.z + v.w * v.w;
    }
    __shared__ float sh1[256], sh2[256];
    int tid = threadIdx.x;
    sh1[tid] = s; sh2[tid] = s2;
    __syncthreads();
    for (int st = 128; st > 0; st >>= 1) {
        if (tid < st) { sh1[tid] += sh1[tid + st]; sh2[tid] += sh2[tid + st]; }
        __syncthreads();
    }
    if (tid == 0) {
        float mean = sh1[0] * (1.f / 32768.f);
        float var  = sh2[0] * (1.f / 32768.f) - mean * mean;
        g_mean[bg] = mean;
        g_rstd[bg] = rsqrtf(var + GN_EPS);
    }
}

// ---------------- kernel 2: xn + Q/K/V projections -------------------------
// One block per (b,h): 64 tokens (all w), C=64.  gamma/beta indexed by h
// (reference broadcasts gamma along dim 1 = H).  Writes xn (token-major),
// Q,K transposed [b][c][t], V token-major.
__global__ void __launch_bounds__(256) gn_qkv_kernel(
    const float* __restrict__ x,
    const float* __restrict__ gamma, const float* __restrict__ beta,
    const float* __restrict__ Wq, const float* __restrict__ bq,
    const float* __restrict__ Wk, const float* __restrict__ bk,
    const float* __restrict__ Wv, const float* __restrict__ bv)
{
    __shared__ float xs[64 * 65];   // xn tile [w][c], stride 65 (conflict-free)
    __shared__ float ws[64 * 64];   // one weight matrix at a time

    int blk = blockIdx.x;           // b*64 + h
    int b = blk >> 6, h = blk & 63, g = h >> 3;
    int tid = threadIdx.x;

    float mean = g_mean[b * GROUPS + g];
    float rstd = g_rstd[b * GROUPS + g];
    float a  = rstd * gamma[h];
    float c0 = beta[h] - mean * a;

    const float4* xp  = (const float4*)(x + (size_t)blk * 4096);
    float4*       xng = (float4*)(g_xn + (size_t)blk * 4096);

    for (int r = 0; r < 4; r++) {
        int i4 = tid + r * 256;
        float4 v = xp[i4];
        v.x = v.x * a + c0; v.y = v.y * a + c0;
        v.z = v.z * a + c0; v.w = v.w * a + c0;
        xng[i4] = v;
        int e = i4 * 4, w = e >> 6, c = e & 63;
        xs[w * 65 + c + 0] = v.x; xs[w * 65 + c + 1] = v.y;
        xs[w * 65 + c + 2] = v.z; xs[w * 65 + c + 3] = v.w;
    }
    __syncthreads();

    // ---- Q and K passes: thread = (w, cb); outputs transposed [b][c][t] ----
    int w = tid & 63, cb = tid >> 6;
    for (int m = 0; m < 2; m++) {
        const float* Wm  = m ? Wk : Wq;
        const float* bm  = m ? bk : bq;
        float*       oT  = m ? g_kT : g_qT;
        __syncthreads();   // ws safe to overwrite
        for (int r = 0; r < 4; r++)
            ((float4*)ws)[tid + r * 256] = ((const float4*)Wm)[tid + r * 256];
        __syncthreads();

        float acc[16];
        #pragma unroll
        for (int c = 0; c < 16; c++) acc[c] = 0.f;
        for (int j = 0; j < 64; j++) {
            float xv = xs[w * 65 + j];
            const float* wr = ws + j * 64 + cb * 16;
            #pragma unroll
            for (int c = 0; c < 16; c++) acc[c] += xv * wr[c];
        }
        #pragma unroll
        for (int c = 0; c < 16; c++) {
            int cc = cb * 16 + c;
            oT[(size_t)(b * 64 + cc) * 4096 + h * 64 + w] = acc[c] + bm[cc];
        }
    }

    // ---- V pass: thread = (c, wb); output token-major [b][t][c] -----------
    __syncthreads();
    for (int r = 0; r < 4; r++)
        ((float4*)ws)[tid + r * 256] = ((const float4*)Wv)[tid + r * 256];
    __syncthreads();
    {
        int c = tid & 63, wb = tid >> 6;
        float acc[16];
        #pragma unroll
        for (int i = 0; i < 16; i++) acc[i] = 0.f;
        for (int j = 0; j < 64; j++) {
            float wv = ws[j * 64 + c];
            #pragma unroll
            for (int i = 0; i < 16; i++)
                acc[i] += xs[(wb * 16 + i) * 65 + j] * wv;
        }
        float bvv = bv[c];
        #pragma unroll
        for (int i = 0; i < 16; i++)
            g_v[((size_t)b * 4096 + h * 64 + wb * 16 + i) * 64 + c] = acc[i] + bvv;
    }
}

// ---------------- kernel 3: flash attention + Wo + residual ----------------
// Block = (b, 64-query tile). 256 threads as 16x16 grid; thread (ty,tx) owns
// a 4x4 register tile. Online softmax; P shared via smem Pt[k][q].
#define SROW 68   // smem row stride (floats): 16B-aligned, conflict-free

__global__ void __launch_bounds__(256) attn_kernel(
    const float* __restrict__ Wo, const float* __restrict__ bo,
    float* __restrict__ out)
{
    extern __shared__ float sm[];
    float* Qts = sm;                  // [d][q]  64 x SROW
    float* Kts = Qts + 64 * SROW;     // [d][k]  (reused for Wo in epilogue)
    float* Vs  = Kts + 64 * SROW;     // [k][d]  64 x 64
    float* Pts = Vs  + 64 * 64;       // [k][q]  64 x SROW (reused for O^T)

    int blk = blockIdx.x;             // b*64 + qtile
    int b = blk >> 6, t0 = (blk & 63) * 64;
    int tid = threadIdx.x, ty = tid >> 4, tx = tid & 15;

    const float* qg = g_qT + (size_t)b * 64 * 4096 + t0;
    const float* kg = g_kT + (size_t)b * 64 * 4096;
    const float* vg = g_v  + (size_t)b * 4096 * 64;

    // load Q tile (transposed layout already): rows=d, cols=q
    for (int r = 0; r < 4; r++) {
        int i4 = tid + r * 256, row = i4 >> 4, col = (i4 & 15) * 4;
        *(float4*)(Qts + row * SROW + col) =
            *(const float4*)(qg + (size_t)row * 4096 + col);
    }

    float o[16], m[4], l[4];
    #pragma unroll
    for (int i = 0; i < 16; i++) o[i] = 0.f;
    #pragma unroll
    for (int i = 0; i < 4; i++) { m[i] = -CUDART_INF_F; l[i] = 0.f; }

    for (int kt = 0; kt < 64; kt++) {
        __syncthreads();   // prev PV done (and Q load visible on first iter)
        int k0 = kt * 64;
        for (int r = 0; r < 4; r++) {
            int i4 = tid + r * 256, row = i4 >> 4, col = (i4 & 15) * 4;
            *(float4*)(Kts + row * SROW + col) =
                *(const float4*)(kg + (size_t)row * 4096 + k0 + col);
            *(float4*)(Vs + i4 * 4) =
                *(const float4*)(vg + (size_t)k0 * 64 + i4 * 4);
        }
        __syncthreads();

        // ---- S = Q^T K tile: s[i][jj], q = ty*4+i, k = tx*4+jj ----
        float s[16];
        #pragma unroll
        for (int i = 0; i < 16; i++) s[i] = 0.f;
        for (int j = 0; j < 64; j++) {
            float4 qv = *(float4*)(Qts + j * SROW + ty * 4);
            float4 kv = *(float4*)(Kts + j * SROW + tx * 4);
            s[0]  += qv.x * kv.x; s[1]  += qv.x * kv.y; s[2]  += qv.x * kv.z; s[3]  += qv.x * kv.w;
            s[4]  += qv.y * kv.x; s[5]  += qv.y * kv.y; s[6]  += qv.y * kv.z; s[7]  += qv.y * kv.w;
            s[8]  += qv.z * kv.x; s[9]  += qv.z * kv.y; s[10] += qv.z * kv.z; s[11] += qv.z * kv.w;
            s[12] += qv.w * kv.x; s[13] += qv.w * kv.y; s[14] += qv.w * kv.z; s[15] += qv.w * kv.w;
        }
        #pragma unroll
        for (int i = 0; i < 16; i++) s[i] *= SCALE;

        // ---- online softmax (row reductions across 16-lane half-warp) ----
        #pragma unroll
        for (int i = 0; i < 4; i++) {
            float tm = fmaxf(fmaxf(s[i*4+0], s[i*4+1]), fmaxf(s[i*4+2], s[i*4+3]));
            #pragma unroll
            for (int off = 8; off > 0; off >>= 1)
                tm = fmaxf(tm, __shfl_xor_sync(0xffffffffu, tm, off));
            float mnew = fmaxf(m[i], tm);
            float corr = __expf(m[i] - mnew);
            l[i] *= corr;
            #pragma unroll
            for (int jj = 0; jj < 4; jj++) o[i*4+jj] *= corr;
            float rs = 0.f;
            #pragma unroll
            for (int jj = 0; jj < 4; jj++) {
                s[i*4+jj] = __expf(s[i*4+jj] - mnew);
                rs += s[i*4+jj];
            }
            #pragma unroll
            for (int off = 8; off > 0; off >>= 1)
                rs += __shfl_xor_sync(0xffffffffu, rs, off);
            l[i] += rs;
            m[i] = mnew;
        }

        // ---- share P transposed: Pt[k][q] (float4 per jj) ----
        #pragma unroll
        for (int jj = 0; jj < 4; jj++) {
            float4 pv = make_float4(s[0*4+jj], s[1*4+jj], s[2*4+jj], s[3*4+jj]);
            *(float4*)(Pts + (tx * 4 + jj) * SROW + ty * 4) = pv;
        }
        __syncthreads();

        // ---- O += P V: o[i][jj], q = ty*4+i, d = tx*4+jj ----
        for (int kk = 0; kk < 64; kk++) {
            float4 pv = *(float4*)(Pts + kk * SROW + ty * 4);
            float4 vv = *(float4*)(Vs + kk * 64 + tx * 4);
            o[0]  += pv.x * vv.x; o[1]  += pv.x * vv.y; o[2]  += pv.x * vv.z; o[3]  += pv.x * vv.w;
            o[4]  += pv.y * vv.x; o[5]  += pv.y * vv.y; o[6]  += pv.y * vv.z; o[7]  += pv.y * vv.w;
            o[8]  += pv.z * vv.x; o[9]  += pv.z * vv.y; o[10] += pv.z * vv.z; o[11] += pv.z * vv.w;
            o[12] += pv.w * vv.x; o[13] += pv.w * vv.y; o[14] += pv.w * vv.z; o[15] += pv.w * vv.w;
        }
    }

    // ---- normalize ----
    #pragma unroll
    for (int i = 0; i < 4; i++) {
        float inv = 1.f / l[i];
        #pragma unroll
        for (int jj = 0; jj < 4; jj++) o[i*4+jj] *= inv;
    }

    __syncthreads();   // PV reads of Pts/Vs done -> safe to reuse
    // O^T into Pts ([d][q]); Wo into Kts ([d][c], stride SROW)
    #pragma unroll
    for (int jj = 0; jj < 4; jj++) {
        float4 ov = make_float4(o[0*4+jj], o[1*4+jj], o[2*4+jj], o[3*4+jj]);
        *(float4*)(Pts + (tx * 4 + jj) * SROW + ty * 4) = ov;
    }
    for (int r = 0; r < 4; r++) {
        int i4 = tid + r * 256, row = i4 >> 4, col = (i4 & 15) * 4;
        *(float4*)(Kts + row * SROW + col) = *(const float4*)(Wo + row * 64 + col);
    }
    __syncthreads();

    // ---- res = O @ Wo : q = ty*4+i, c = tx*4+jj ----
    float res[16];
    #pragma unroll
    for (int i = 0; i < 16; i++) res[i] = 0.f;
    for (int d = 0; d < 64; d++) {
        float4 ov = *(float4*)(Pts + d * SROW + ty * 4);
        float4 wv = *(float4*)(Kts + d * SROW + tx * 4);
        res[0]  += ov.x * wv.x; res[1]  += ov.x * wv.y; res[2]  += ov.x * wv.z; res[3]  += ov.x * wv.w;
        res[4]  += ov.y * wv.x; res[5]  += ov.y * wv.y; res[6]  += ov.y * wv.z; res[7]  += ov.y * wv.w;
        res[8]  += ov.z * wv.x; res[9]  += ov.z * wv.y; res[10] += ov.z * wv.z; res[11] += ov.z * wv.w;
        res[12] += ov.w * wv.x; res[13] += ov.w * wv.y; res[14] += ov.w * wv.z; res[15] += ov.w * wv.w;
    }

    float4 bov = *(const float4*)(bo + tx * 4);
    #pragma unroll
    for (int i = 0; i < 4; i++) {
        size_t base = ((size_t)b * 4096 + t0 + ty * 4 + i) * 64 + tx * 4;
        float4 xnv = *(const float4*)(g_xn + base);
        float4 r4;
        r4.x = res[i*4+0] + bov.x + xnv.x;
        r4.y = res[i*4+1] + bov.y + xnv.y;
        r4.z = res[i*4+2] + bov.z + xnv.z;
        r4.w = res[i*4+3] + bov.w + xnv.w;
        *(float4*)(out + base) = r4;
    }
}

// ---------------- launch ----------------------------------------------------
extern "C" void kernel_launch(void* const* d_in, const int* in_sizes, int n_in,
                              void* d_out, int out_size)
{
    const float* x     = (const float*)d_in[0];
    const float* gamma = (const float*)d_in[1];
    const float* beta  = (const float*)d_in[2];
    const float* Wq    = (const float*)d_in[3];
    const float* bq    = (const float*)d_in[4];
    const float* Wk    = (const float*)d_in[5];
    const float* bk    = (const float*)d_in[6];
    const float* Wv    = (const float*)d_in[7];
    const float* bv    = (const float*)d_in[8];
    const float* Wo    = (const float*)d_in[9];
    const float* bo    = (const float*)d_in[10];
    float* out = (float*)d_out;

    const int attn_smem = (64 * SROW + 64 * SROW + 64 * 64 + 64 * SROW) * 4; // 68608 B
    cudaFuncSetAttribute(attn_kernel,
                         cudaFuncAttributeMaxDynamicSharedMemorySize, attn_smem);

    gn_stats_kernel<<<BATCH * GROUPS, 256>>>(x);
    gn_qkv_kernel<<<BATCH * HDIM, 256>>>(x, gamma, beta, Wq, bq, Wk, bk, Wv, bv);
    attn_kernel<<<BATCH * (SEQ / 64), 256, attn_smem>>>(Wo, bo, out);
}

// round 2
// speedup vs baseline: 3.7399x; 3.7399x over previous
#include <cuda_runtime.h>
#include <cuda_bf16.h>
#include <math_constants.h>

// Problem constants: B=4, H=64, W=64, C=64, GROUPS=8
#define BATCH 4
#define GROUPS 8
#define SEQ 4096
#define NTOK (BATCH * SEQ)
#define GN_EPS 1e-5f
#define SCALE 0.125f

// ---------------- scratch ---------------------------------------------------
__device__ float g_mean[BATCH * GROUPS];
__device__ float g_rstd[BATCH * GROUPS];
__device__ float g_xn[NTOK * 64];                        // fp32 [b][t][c]
__device__ __nv_bfloat16 g_qb[NTOK * 64];                // bf16 [b][t][d]
__device__ __nv_bfloat16 g_kb[NTOK * 64];                // bf16 [b][t][d]
__device__ __nv_bfloat16 g_vtb[BATCH * 64 * SEQ];        // bf16 [b][d][t]
__device__ __nv_bfloat16 g_woT[64 * 64];                 // bf16 [out][in]

// ---------------- PTX helpers ----------------------------------------------
#define LDSM4(r0, r1, r2, r3, addr)                                          \
    asm volatile("ldmatrix.sync.aligned.m8n8.x4.shared.b16 {%0,%1,%2,%3}, [%4];" \
                 : "=r"(r0), "=r"(r1), "=r"(r2), "=r"(r3) : "r"(addr))

#define MMA16816(d, a0, a1, a2, a3, b0, b1)                                  \
    asm volatile("mma.sync.aligned.m16n8k16.row.col.f32.bf16.bf16.f32 "      \
                 "{%0,%1,%2,%3}, {%4,%5,%6,%7}, {%8,%9}, {%0,%1,%2,%3};"     \
                 : "+f"(d[0]), "+f"(d[1]), "+f"(d[2]), "+f"(d[3])            \
                 : "r"(a0), "r"(a1), "r"(a2), "r"(a3), "r"(b0), "r"(b1))

__device__ __forceinline__ unsigned pk2(float hi, float lo) {
    unsigned d;
    asm("cvt.rn.bf16x2.f32 %0, %1, %2;" : "=r"(d) : "f"(hi), "f"(lo));
    return d;
}

// ---------------- kernel 1: group-norm statistics ---------------------------
__global__ void gn_stats_kernel(const float* __restrict__ x) {
    int bg = blockIdx.x;
    const float4* p = (const float4*)(x + (size_t)bg * 32768);
    float s = 0.f, s2 = 0.f;
    for (int i = threadIdx.x; i < 8192; i += 256) {
        float4 v = p[i];
        s  += v.x + v.y + v.z + v.w;
        s2 += v.x * v.x + v.y * v.y + v.z * v.z + v.w * v.w;
    }
    __shared__ float sh1[256], sh2[256];
    int tid = threadIdx.x;
    sh1[tid] = s; sh2[tid] = s2;
    __syncthreads();
    for (int st = 128; st > 0; st >>= 1) {
        if (tid < st) { sh1[tid] += sh1[tid + st]; sh2[tid] += sh2[tid + st]; }
        __syncthreads();
    }
    if (tid == 0) {
        float mean = sh1[0] * (1.f / 32768.f);
        float var  = sh2[0] * (1.f / 32768.f) - mean * mean;
        g_mean[bg] = mean;
        g_rstd[bg] = rsqrtf(var + GN_EPS);
    }
}

// ---------------- kernel 1b: Wo transpose to bf16 ---------------------------
__global__ void wo_prep_kernel(const float* __restrict__ Wo) {
    for (int i = threadIdx.x; i < 4096; i += 256) {
        int o = i & 63, in = i >> 6;
        g_woT[o * 64 + in] = __float2bfloat16(Wo[in * 64 + o]);
    }
}

// ---------------- kernel 2: xn + Q/K/V projections --------------------------
__global__ void __launch_bounds__(256) gn_qkv_kernel(
    const float* __restrict__ x,
    const float* __restrict__ gamma, const float* __restrict__ beta,
    const float* __restrict__ Wq, const float* __restrict__ bq,
    const float* __restrict__ Wk, const float* __restrict__ bk,
    const float* __restrict__ Wv, const float* __restrict__ bv)
{
    __shared__ float xs[64 * 65];
    __shared__ float ws[64 * 64];

    int blk = blockIdx.x;             // b*64 + h
    int b = blk >> 6, h = blk & 63, gg = h >> 3;
    int tid = threadIdx.x;

    float mean = g_mean[b * GROUPS + gg];
    float rstd = g_rstd[b * GROUPS + gg];
    float a  = rstd * gamma[h];
    float c0 = beta[h] - mean * a;

    const float4* xp  = (const float4*)(x + (size_t)blk * 4096);
    float4*       xng = (float4*)(g_xn + (size_t)blk * 4096);

    for (int r = 0; r < 4; r++) {
        int i4 = tid + r * 256;
        float4 v = xp[i4];
        v.x = v.x * a + c0; v.y = v.y * a + c0;
        v.z = v.z * a + c0; v.w = v.w * a + c0;
        xng[i4] = v;
        int e = i4 * 4, w = e >> 6, c = e & 63;
        xs[w * 65 + c + 0] = v.x; xs[w * 65 + c + 1] = v.y;
        xs[w * 65 + c + 2] = v.z; xs[w * 65 + c + 3] = v.w;
    }
    __syncthreads();

    // ---- Q and K: token-major bf16; thread = (c, wb) -----------------------
    for (int mtx = 0; mtx < 2; mtx++) {
        const float* Wm = mtx ? Wk : Wq;
        const float* bm = mtx ? bk : bq;
        __nv_bfloat16* og = mtx ? g_kb : g_qb;
        for (int r = 0; r < 4; r++)
            ((float4*)ws)[tid + r * 256] = ((const float4*)Wm)[tid + r * 256];
        __syncthreads();

        int c = tid & 63, wb = tid >> 6;
        float acc[16];
        #pragma unroll
        for (int i = 0; i < 16; i++) acc[i] = 0.f;
        for (int j = 0; j < 64; j++) {
            float wv = ws[j * 64 + c];
            #pragma unroll
            for (int i = 0; i < 16; i++)
                acc[i] += xs[(wb * 16 + i) * 65 + j] * wv;
        }
        float bb = bm[c];
        #pragma unroll
        for (int i = 0; i < 16; i++)
            og[((size_t)b * 4096 + h * 64 + wb * 16 + i) * 64 + c] =
                __float2bfloat16(acc[i] + bb);
        __syncthreads();
    }

    // ---- V: transposed [b][d][t] bf16; thread = (w, cb) --------------------
    for (int r = 0; r < 4; r++)
        ((float4*)ws)[tid + r * 256] = ((const float4*)Wv)[tid + r * 256];
    __syncthreads();
    {
        int w = tid & 63, cb = tid >> 6;
        float acc[16];
        #pragma unroll
        for (int c = 0; c < 16; c++) acc[c] = 0.f;
        for (int j = 0; j < 64; j++) {
            float xv = xs[w * 65 + j];
            const float* wr = ws + j * 64 + cb * 16;
            #pragma unroll
            for (int c = 0; c < 16; c++) acc[c] += xv * wr[c];
        }
        #pragma unroll
        for (int c = 0; c < 16; c++) {
            int cc = cb * 16 + c;
            g_vtb[(size_t)(b * 64 + cc) * 4096 + h * 64 + w] =
                __float2bfloat16(acc[c] + bv[cc]);
        }
    }
}

// ---------------- kernel 3: flash attention (bf16 mma) ----------------------
// Block: 256 threads = 8 warps, 128 queries (16/warp). Key tiles of 64.
#define SSTR 72   // smem row stride in bf16 (144B -> conflict-free LDSM)

__global__ void __launch_bounds__(256) attn_kernel(
    const float* __restrict__ bo, float* __restrict__ out)
{
    __shared__ __align__(16) __nv_bfloat16 Qs[128 * SSTR];
    __shared__ __align__(16) __nv_bfloat16 Ks[64 * SSTR];   // reused for WoT
    __shared__ __align__(16) __nv_bfloat16 Vts[64 * SSTR];

    int b = blockIdx.x >> 5, qt = blockIdx.x & 31;
    int t0 = qt * 128;
    int tid = threadIdx.x;
    int warp = tid >> 5, lane = tid & 31;
    int qr = warp * 16;
    int g = lane >> 2, c4 = lane & 3;

    const __nv_bfloat16* qg  = g_qb  + ((size_t)b * 4096 + t0) * 64;
    const __nv_bfloat16* kgb = g_kb  + (size_t)b * 4096 * 64;
    const __nv_bfloat16* vtg = g_vtb + (size_t)b * 64 * 4096;

    // load Q tile (128 x 64 bf16)
    for (int i = tid; i < 1024; i += 256) {
        int row = i >> 3, cc = i & 7;
        *(float4*)(Qs + row * SSTR + cc * 8) =
            *(const float4*)(qg + row * 64 + cc * 8);
    }
    __syncthreads();

    unsigned qbase = (unsigned)__cvta_generic_to_shared(Qs);
    unsigned kbase = (unsigned)__cvta_generic_to_shared(Ks);
    unsigned vbase = (unsigned)__cvta_generic_to_shared(Vts);

    // A-frag addressing (m16k16 tile at (qr, k0)): mats [r0-7|r8-15] x [c0|c8]
    int arow = (lane & 7) + (lane & 8);
    int acol = (lane >> 4) << 3;
    unsigned aaddr = qbase + (unsigned)(((qr + arow) * SSTR + acol) * 2);
    unsigned aQ[4][4];
    #pragma unroll
    for (int kk = 0; kk < 4; kk++)
        LDSM4(aQ[kk][0], aQ[kk][1], aQ[kk][2], aQ[kk][3], aaddr + kk * 32);

    // B-frag per-lane offset (rows=n, cols=k): mats [n0-7,k0][n0-7,k8][n8-15,k0][n8-15,k8]
    unsigned boff = (unsigned)((((lane & 7) + ((lane & 16) >> 1)) * SSTR + (lane & 8)) * 2);

    float of[8][4];
    #pragma unroll
    for (int nn = 0; nn < 8; nn++)
        #pragma unroll
        for (int i = 0; i < 4; i++) of[nn][i] = 0.f;
    float m0 = -CUDART_INF_F, m1 = -CUDART_INF_F, l0 = 0.f, l1 = 0.f;

    for (int kt = 0; kt < 64; kt++) {
        __syncthreads();     // previous tile fully consumed
        const __nv_bfloat16* kg = kgb + (size_t)kt * 64 * 64;
        for (int i = tid; i < 512; i += 256) {
            int row = i >> 3, cc = i & 7;
            *(float4*)(Ks  + row * SSTR + cc * 8) =
                *(const float4*)(kg + row * 64 + cc * 8);
            *(float4*)(Vts + row * SSTR + cc * 8) =
                *(const float4*)(vtg + (size_t)row * 4096 + kt * 64 + cc * 8);
        }
        __syncthreads();

        // ---- S = Q K^T (16 x 64 per warp) ----
        float s[8][4];
        #pragma unroll
        for (int nn = 0; nn < 8; nn++)
            #pragma unroll
            for (int i = 0; i < 4; i++) s[nn][i] = 0.f;
        #pragma unroll
        for (int kk = 0; kk < 4; kk++) {
            #pragma unroll
            for (int np = 0; np < 4; np++) {
                unsigned b0, b1, b2, b3;
                LDSM4(b0, b1, b2, b3,
                      kbase + boff + (unsigned)((np * 16 * SSTR + kk * 16) * 2));
                MMA16816(s[2 * np],     aQ[kk][0], aQ[kk][1], aQ[kk][2], aQ[kk][3], b0, b1);
                MMA16816(s[2 * np + 1], aQ[kk][0], aQ[kk][1], aQ[kk][2], aQ[kk][3], b2, b3);
            }
        }
        #pragma unroll
        for (int nn = 0; nn < 8; nn++)
            #pragma unroll
            for (int i = 0; i < 4; i++) s[nn][i] *= SCALE;

        // ---- online softmax (rows g and g+8; quad shfl reduce) ----
        float tm0 = -CUDART_INF_F, tm1 = -CUDART_INF_F;
        #pragma unroll
        for (int nn = 0; nn < 8; nn++) {
            tm0 = fmaxf(tm0, fmaxf(s[nn][0], s[nn][1]));
            tm1 = fmaxf(tm1, fmaxf(s[nn][2], s[nn][3]));
        }
        tm0 = fmaxf(tm0, __shfl_xor_sync(0xffffffffu, tm0, 1));
        tm0 = fmaxf(tm0, __shfl_xor_sync(0xffffffffu, tm0, 2));
        tm1 = fmaxf(tm1, __shfl_xor_sync(0xffffffffu, tm1, 1));
        tm1 = fmaxf(tm1, __shfl_xor_sync(0xffffffffu, tm1, 2));
        float mn0 = fmaxf(m0, tm0), mn1 = fmaxf(m1, tm1);
        float corr0 = __expf(m0 - mn0), corr1 = __expf(m1 - mn1);
        float rs0 = 0.f, rs1 = 0.f;
        #pragma unroll
        for (int nn = 0; nn < 8; nn++) {
            s[nn][0] = __expf(s[nn][0] - mn0);
            s[nn][1] = __expf(s[nn][1] - mn0);
            s[nn][2] = __expf(s[nn][2] - mn1);
            s[nn][3] = __expf(s[nn][3] - mn1);
            rs0 += s[nn][0] + s[nn][1];
            rs1 += s[nn][2] + s[nn][3];
        }
        rs0 += __shfl_xor_sync(0xffffffffu, rs0, 1);
        rs0 += __shfl_xor_sync(0xffffffffu, rs0, 2);
        rs1 += __shfl_xor_sync(0xffffffffu, rs1, 1);
        rs1 += __shfl_xor_sync(0xffffffffu, rs1, 2);
        l0 = l0 * corr0 + rs0; l1 = l1 * corr1 + rs1;
        m0 = mn0; m1 = mn1;
        #pragma unroll
        for (int nn = 0; nn < 8; nn++) {
            of[nn][0] *= corr0; of[nn][1] *= corr0;
            of[nn][2] *= corr1; of[nn][3] *= corr1;
        }

        // ---- O += P V  (P packed from C-frags; B from V^T) ----
        #pragma unroll
        for (int kk = 0; kk < 4; kk++) {
            unsigned a0 = pk2(s[2 * kk][1],     s[2 * kk][0]);
            unsigned a1 = pk2(s[2 * kk][3],     s[2 * kk][2]);
            unsigned a2 = pk2(s[2 * kk + 1][1], s[2 * kk + 1][0]);
            unsigned a3 = pk2(s[2 * kk + 1][3], s[2 * kk + 1][2]);
            #pragma unroll
            for (int np = 0; np < 4; np++) {
                unsigned b0, b1, b2, b3;
                LDSM4(b0, b1, b2, b3,
                      vbase + boff + (unsigned)((np * 16 * SSTR + kk * 16) * 2));
                MMA16816(of[2 * np],     a0, a1, a2, a3, b0, b1);
                MMA16816(of[2 * np + 1], a0, a1, a2, a3, b2, b3);
            }
        }
    }

    // ---- epilogue: res = (O/l) @ Wo + bo + xn ----
    __syncthreads();
    for (int i = tid; i < 512; i += 256) {
        int row = i >> 3, cc = i & 7;
        *(float4*)(Ks + row * SSTR + cc * 8) =
            *(const float4*)(g_woT + row * 64 + cc * 8);
    }
    __syncthreads();

    float inv0 = 1.f / l0, inv1 = 1.f / l1;
    #pragma unroll
    for (int nn = 0; nn < 8; nn++) {
        of[nn][0] *= inv0; of[nn][1] *= inv0;
        of[nn][2] *= inv1; of[nn][3] *= inv1;
    }

    float r[8][4];
    #pragma unroll
    for (int nn = 0; nn < 8; nn++)
        #pragma unroll
        for (int i = 0; i < 4; i++) r[nn][i] = 0.f;
    #pragma unroll
    for (int kk = 0; kk < 4; kk++) {
        unsigned a0 = pk2(of[2 * kk][1],     of[2 * kk][0]);
        unsigned a1 = pk2(of[2 * kk][3],     of[2 * kk][2]);
        unsigned a2 = pk2(of[2 * kk + 1][1], of[2 * kk + 1][0]);
        unsigned a3 = pk2(of[2 * kk + 1][3], of[2 * kk + 1][2]);
        #pragma unroll
        for (int np = 0; np < 4; np++) {
            unsigned b0, b1, b2, b3;
            LDSM4(b0, b1, b2, b3,
                  kbase + boff + (unsigned)((np * 16 * SSTR + kk * 16) * 2));
            MMA16816(r[2 * np],     a0, a1, a2, a3, b0, b1);
            MMA16816(r[2 * np + 1], a0, a1, a2, a3, b2, b3);
        }
    }

    #pragma unroll
    for (int nn = 0; nn < 8; nn++) {
        int col = nn * 8 + c4 * 2;
        float2 bv = *(const float2*)(bo + col);
        size_t i0 = ((size_t)b * 4096 + t0 + qr + g) * 64 + col;
        float2 x0 = *(const float2*)(g_xn + i0);
        float2 o0 = make_float2(r[nn][0] + bv.x + x0.x, r[nn][1] + bv.y + x0.y);
        *(float2*)(out + i0) = o0;
        size_t i1 = i0 + (size_t)8 * 64;
        float2 x1 = *(const float2*)(g_xn + i1);
        float2 o1 = make_float2(r[nn][2] + bv.x + x1.x, r[nn][3] + bv.y + x1.y);
        *(float2*)(out + i1) = o1;
    }
}

// ---------------- launch ----------------------------------------------------
extern "C" void kernel_launch(void* const* d_in, const int* in_sizes, int n_in,
                              void* d_out, int out_size)
{
    const float* x     = (const float*)d_in[0];
    const float* gamma = (const float*)d_in[1];
    const float* beta  = (const float*)d_in[2];
    const float* Wq    = (const float*)d_in[3];
    const float* bq    = (const float*)d_in[4];
    const float* Wk    = (const float*)d_in[5];
    const float* bk    = (const float*)d_in[6];
    const float* Wv    = (const float*)d_in[7];
    const float* bv    = (const float*)d_in[8];
    const float* Wo    = (const float*)d_in[9];
    const float* bo    = (const float*)d_in[10];
    float* out = (float*)d_out;

    gn_stats_kernel<<<BATCH * GROUPS, 256>>>(x);
    wo_prep_kernel<<<1, 256>>>(Wo);
    gn_qkv_kernel<<<BATCH * 64, 256>>>(x, gamma, beta, Wq, bq, Wk, bk, Wv, bv);
    attn_kernel<<<BATCH * 32, 256>>>(bo, out);
}

// round 3
// speedup vs baseline: 5.1106x; 1.3665x over previous
#include <cuda_runtime.h>
#include <cuda_bf16.h>
#include <math_constants.h>

// Problem constants: B=4, H=64, W=64, C=64, GROUPS=8
#define BATCH 4
#define GROUPS 8
#define SEQ 4096
#define NTOK (BATCH * SEQ)
#define GN_EPS 1e-5f
#define SCALE 0.125f
#define LOG2E 1.4426950408889634f

// ---------------- scratch ---------------------------------------------------
__device__ float g_mean[BATCH * GROUPS];
__device__ float g_rstd[BATCH * GROUPS];
__device__ float g_xn[NTOK * 64];                        // fp32 [b][t][c]
__device__ __nv_bfloat16 g_qb[NTOK * 64];                // bf16 [b][t][d]
__device__ __nv_bfloat16 g_kb[NTOK * 64];                // bf16 [b][t][d]
__device__ __nv_bfloat16 g_vtb[BATCH * 64 * SEQ];        // bf16 [b][d][t]
__device__ __nv_bfloat16 g_woT[64 * 64];                 // bf16 [out][in]

// ---------------- PTX helpers ----------------------------------------------
#define LDSM4(r0, r1, r2, r3, addr)                                          \
    asm volatile("ldmatrix.sync.aligned.m8n8.x4.shared.b16 {%0,%1,%2,%3}, [%4];" \
                 : "=r"(r0), "=r"(r1), "=r"(r2), "=r"(r3) : "r"(addr))

#define MMA16816(d, a0, a1, a2, a3, b0, b1)                                  \
    asm volatile("mma.sync.aligned.m16n8k16.row.col.f32.bf16.bf16.f32 "      \
                 "{%0,%1,%2,%3}, {%4,%5,%6,%7}, {%8,%9}, {%0,%1,%2,%3};"     \
                 : "+f"(d[0]), "+f"(d[1]), "+f"(d[2]), "+f"(d[3])            \
                 : "r"(a0), "r"(a1), "r"(a2), "r"(a3), "r"(b0), "r"(b1))

#define CP_ASYNC16(dst, src)                                                 \
    asm volatile("cp.async.cg.shared.global [%0], [%1], 16;"                 \
                 :: "r"(dst), "l"(src))
#define CP_COMMIT()  asm volatile("cp.async.commit_group;")
#define CP_WAIT1()   asm volatile("cp.async.wait_group 1;")

__device__ __forceinline__ unsigned pk2(float hi, float lo) {
    unsigned d;
    asm("cvt.rn.bf16x2.f32 %0, %1, %2;" : "=r"(d) : "f"(hi), "f"(lo));
    return d;
}
__device__ __forceinline__ float ex2(float x) {
    float r;
    asm("ex2.approx.f32 %0, %1;" : "=f"(r) : "f"(x));
    return r;
}

// ---------------- kernel 1: group-norm statistics ---------------------------
__global__ void gn_stats_kernel(const float* __restrict__ x) {
    int bg = blockIdx.x;
    const float4* p = (const float4*)(x + (size_t)bg * 32768);
    float s = 0.f, s2 = 0.f;
    for (int i = threadIdx.x; i < 8192; i += 256) {
        float4 v = p[i];
        s  += v.x + v.y + v.z + v.w;
        s2 += v.x * v.x + v.y * v.y + v.z * v.z + v.w * v.w;
    }
    __shared__ float sh1[256], sh2[256];
    int tid = threadIdx.x;
    sh1[tid] = s; sh2[tid] = s2;
    __syncthreads();
    for (int st = 128; st > 0; st >>= 1) {
        if (tid < st) { sh1[tid] += sh1[tid + st]; sh2[tid] += sh2[tid + st]; }
        __syncthreads();
    }
    if (tid == 0) {
        float mean = sh1[0] * (1.f / 32768.f);
        float var  = sh2[0] * (1.f / 32768.f) - mean * mean;
        g_mean[bg] = mean;
        g_rstd[bg] = rsqrtf(var + GN_EPS);
    }
}

// ---------------- kernel 1b: Wo transpose to bf16 ---------------------------
__global__ void wo_prep_kernel(const float* __restrict__ Wo) {
    for (int i = threadIdx.x; i < 4096; i += 256) {
        int o = i & 63, in = i >> 6;
        g_woT[o * 64 + in] = __float2bfloat16(Wo[in * 64 + o]);
    }
}

// ---------------- kernel 2: xn + Q/K/V projections --------------------------
__global__ void __launch_bounds__(256) gn_qkv_kernel(
    const float* __restrict__ x,
    const float* __restrict__ gamma, const float* __restrict__ beta,
    const float* __restrict__ Wq, const float* __restrict__ bq,
    const float* __restrict__ Wk, const float* __restrict__ bk,
    const float* __restrict__ Wv, const float* __restrict__ bv)
{
    __shared__ float xs[64 * 65];
    __shared__ float ws[64 * 64];

    int blk = blockIdx.x;             // b*64 + h
    int b = blk >> 6, h = blk & 63, gg = h >> 3;
    int tid = threadIdx.x;

    float mean = g_mean[b * GROUPS + gg];
    float rstd = g_rstd[b * GROUPS + gg];
    float a  = rstd * gamma[h];
    float c0 = beta[h] - mean * a;

    const float4* xp  = (const float4*)(x + (size_t)blk * 4096);
    float4*       xng = (float4*)(g_xn + (size_t)blk * 4096);

    for (int r = 0; r < 4; r++) {
        int i4 = tid + r * 256;
        float4 v = xp[i4];
        v.x = v.x * a + c0; v.y = v.y * a + c0;
        v.z = v.z * a + c0; v.w = v.w * a + c0;
        xng[i4] = v;
        int e = i4 * 4, w = e >> 6, c = e & 63;
        xs[w * 65 + c + 0] = v.x; xs[w * 65 + c + 1] = v.y;
        xs[w * 65 + c + 2] = v.z; xs[w * 65 + c + 3] = v.w;
    }
    __syncthreads();

    // ---- Q and K: token-major bf16; thread = (c, wb) -----------------------
    for (int mtx = 0; mtx < 2; mtx++) {
        const float* Wm = mtx ? Wk : Wq;
        const float* bm = mtx ? bk : bq;
        __nv_bfloat16* og = mtx ? g_kb : g_qb;
        for (int r = 0; r < 4; r++)
            ((float4*)ws)[tid + r * 256] = ((const float4*)Wm)[tid + r * 256];
        __syncthreads();

        int c = tid & 63, wb = tid >> 6;
        float acc[16];
        #pragma unroll
        for (int i = 0; i < 16; i++) acc[i] = 0.f;
        for (int j = 0; j < 64; j++) {
            float wv = ws[j * 64 + c];
            #pragma unroll
            for (int i = 0; i < 16; i++)
                acc[i] += xs[(wb * 16 + i) * 65 + j] * wv;
        }
        float bb = bm[c];
        #pragma unroll
        for (int i = 0; i < 16; i++)
            og[((size_t)b * 4096 + h * 64 + wb * 16 + i) * 64 + c] =
                __float2bfloat16(acc[i] + bb);
        __syncthreads();
    }

    // ---- V: transposed [b][d][t] bf16; thread = (w, cb) --------------------
    for (int r = 0; r < 4; r++)
        ((float4*)ws)[tid + r * 256] = ((const float4*)Wv)[tid + r * 256];
    __syncthreads();
    {
        int w = tid & 63, cb = tid >> 6;
        float acc[16];
        #pragma unroll
        for (int c = 0; c < 16; c++) acc[c] = 0.f;
        for (int j = 0; j < 64; j++) {
            float xv = xs[w * 65 + j];
            const float* wr = ws + j * 64 + cb * 16;
            #pragma unroll
            for (int c = 0; c < 16; c++) acc[c] += xv * wr[c];
        }
        #pragma unroll
        for (int c = 0; c < 16; c++) {
            int cc = cb * 16 + c;
            g_vtb[(size_t)(b * 64 + cc) * 4096 + h * 64 + w] =
                __float2bfloat16(acc[c] + bv[cc]);
        }
    }
}

// ---------------- kernel 3: flash attention (bf16 mma, cp.async pipeline) ---
// Block: 256 threads = 8 warps, 128 queries (16/warp). Key tiles of 64,
// double-buffered via cp.async.
#define SSTR 72                    // smem row stride in bf16 (144B)
#define KVB  (64 * SSTR * 2)       // bytes per K (or V) buffer stage

__global__ void __launch_bounds__(256) attn_kernel(
    const float* __restrict__ bo, float* __restrict__ out)
{
    extern __shared__ __align__(16) __nv_bfloat16 dsm[];
    __nv_bfloat16* Qs  = dsm;                   // 128 x SSTR
    __nv_bfloat16* Ks  = Qs + 128 * SSTR;       // 2 stages, 64 x SSTR each
    __nv_bfloat16* Vts = Ks + 2 * 64 * SSTR;    // 2 stages, 64 x SSTR each

    int b = blockIdx.x >> 5, qt = blockIdx.x & 31;
    int t0 = qt * 128;
    int tid = threadIdx.x;
    int warp = tid >> 5, lane = tid & 31;
    int qr = warp * 16;
    int g = lane >> 2, c4 = lane & 3;

    const __nv_bfloat16* qg  = g_qb  + ((size_t)b * 4096 + t0) * 64;
    const __nv_bfloat16* kgb = g_kb  + (size_t)b * 4096 * 64;
    const __nv_bfloat16* vtg = g_vtb + (size_t)b * 64 * 4096;

    unsigned qbase = (unsigned)__cvta_generic_to_shared(Qs);
    unsigned kbase = (unsigned)__cvta_generic_to_shared(Ks);
    unsigned vbase = (unsigned)__cvta_generic_to_shared(Vts);

    // per-thread load coordinates (2 chunks of 16B per 64x64 tile)
    int lrow0 = tid >> 3,          lcc0 = tid & 7;
    int lrow1 = (tid + 256) >> 3,  lcc1 = tid & 7;

    // load Q tile (128 x 64 bf16) via cp.async
    for (int i = tid; i < 1024; i += 256) {
        int row = i >> 3, cc = i & 7;
        CP_ASYNC16(qbase + (unsigned)((row * SSTR + cc * 8) * 2),
                   qg + row * 64 + cc * 8);
    }
    // prefetch key tile 0 into stage 0
    {
        const __nv_bfloat16* kg = kgb;
        CP_ASYNC16(kbase + (unsigned)((lrow0 * SSTR + lcc0 * 8) * 2), kg + lrow0 * 64 + lcc0 * 8);
        CP_ASYNC16(kbase + (unsigned)((lrow1 * SSTR + lcc1 * 8) * 2), kg + lrow1 * 64 + lcc1 * 8);
        CP_ASYNC16(vbase + (unsigned)((lrow0 * SSTR + lcc0 * 8) * 2), vtg + (size_t)lrow0 * 4096 + lcc0 * 8);
        CP_ASYNC16(vbase + (unsigned)((lrow1 * SSTR + lcc1 * 8) * 2), vtg + (size_t)lrow1 * 4096 + lcc1 * 8);
    }
    CP_COMMIT();

    // wait for Q (group with Q and tile0 is the only one) then ldsm A frags
    asm volatile("cp.async.wait_group 0;");
    __syncthreads();

    int arow = (lane & 7) + (lane & 8);
    int acol = (lane >> 4) << 3;
    unsigned aaddr = qbase + (unsigned)(((qr + arow) * SSTR + acol) * 2);
    unsigned aQ[4][4];
    #pragma unroll
    for (int kk = 0; kk < 4; kk++)
        LDSM4(aQ[kk][0], aQ[kk][1], aQ[kk][2], aQ[kk][3], aaddr + kk * 32);

    unsigned boff = (unsigned)((((lane & 7) + ((lane & 16) >> 1)) * SSTR + (lane & 8)) * 2);

    float of[8][4];
    #pragma unroll
    for (int nn = 0; nn < 8; nn++)
        #pragma unroll
        for (int i = 0; i < 4; i++) of[nn][i] = 0.f;
    float m0 = -CUDART_INF_F, m1 = -CUDART_INF_F, l0 = 0.f, l1 = 0.f;
    const float SC2 = SCALE * LOG2E;

    for (int kt = 0; kt < 64; kt++) {
        __syncthreads();   // all warps done with compute(kt-1): safe to refill its buffer
        // prefetch tile kt+1 into the other stage
        if (kt + 1 < 64) {
            int s1 = (kt + 1) & 1;
            const __nv_bfloat16* kg = kgb + (size_t)(kt + 1) * 64 * 64;
            const __nv_bfloat16* vg = vtg + (size_t)(kt + 1) * 64;
            unsigned kd = kbase + (unsigned)(s1 * KVB);
            unsigned vd = vbase + (unsigned)(s1 * KVB);
            CP_ASYNC16(kd + (unsigned)((lrow0 * SSTR + lcc0 * 8) * 2), kg + lrow0 * 64 + lcc0 * 8);
            CP_ASYNC16(kd + (unsigned)((lrow1 * SSTR + lcc1 * 8) * 2), kg + lrow1 * 64 + lcc1 * 8);
            CP_ASYNC16(vd + (unsigned)((lrow0 * SSTR + lcc0 * 8) * 2), vg + (size_t)lrow0 * 4096 + lcc0 * 8);
            CP_ASYNC16(vd + (unsigned)((lrow1 * SSTR + lcc1 * 8) * 2), vg + (size_t)lrow1 * 4096 + lcc1 * 8);
        }
        CP_COMMIT();
        CP_WAIT1();        // tile kt resident (tile kt+1 still in flight)
        __syncthreads();

        int s0 = kt & 1;
        unsigned kb = kbase + (unsigned)(s0 * KVB) + boff;
        unsigned vb = vbase + (unsigned)(s0 * KVB) + boff;

        // ---- S = Q K^T (16 x 64 per warp), scaled into log2 domain ----
        float s[8][4];
        #pragma unroll
        for (int nn = 0; nn < 8; nn++)
            #pragma unroll
            for (int i = 0; i < 4; i++) s[nn][i] = 0.f;
        #pragma unroll
        for (int kk = 0; kk < 4; kk++) {
            #pragma unroll
            for (int np = 0; np < 4; np++) {
                unsigned b0, b1, b2, b3;
                LDSM4(b0, b1, b2, b3, kb + (unsigned)((np * 16 * SSTR + kk * 16) * 2));
                MMA16816(s[2 * np],     aQ[kk][0], aQ[kk][1], aQ[kk][2], aQ[kk][3], b0, b1);
                MMA16816(s[2 * np + 1], aQ[kk][0], aQ[kk][1], aQ[kk][2], aQ[kk][3], b2, b3);
            }
        }
        #pragma unroll
        for (int nn = 0; nn < 8; nn++)
            #pragma unroll
            for (int i = 0; i < 4; i++) s[nn][i] *= SC2;

        // ---- online softmax in log2 domain (rows g, g+8) ----
        float tm0 = -CUDART_INF_F, tm1 = -CUDART_INF_F;
        #pragma unroll
        for (int nn = 0; nn < 8; nn++) {
            tm0 = fmaxf(tm0, fmaxf(s[nn][0], s[nn][1]));
            tm1 = fmaxf(tm1, fmaxf(s[nn][2], s[nn][3]));
        }
        tm0 = fmaxf(tm0, __shfl_xor_sync(0xffffffffu, tm0, 1));
        tm0 = fmaxf(tm0, __shfl_xor_sync(0xffffffffu, tm0, 2));
        tm1 = fmaxf(tm1, __shfl_xor_sync(0xffffffffu, tm1, 1));
        tm1 = fmaxf(tm1, __shfl_xor_sync(0xffffffffu, tm1, 2));
        float mn0 = fmaxf(m0, tm0), mn1 = fmaxf(m1, tm1);
        float corr0 = ex2(m0 - mn0), corr1 = ex2(m1 - mn1);
        float rs0 = 0.f, rs1 = 0.f;
        #pragma unroll
        for (int nn = 0; nn < 8; nn++) {
            s[nn][0] = ex2(s[nn][0] - mn0);
            s[nn][1] = ex2(s[nn][1] - mn0);
            s[nn][2] = ex2(s[nn][2] - mn1);
            s[nn][3] = ex2(s[nn][3] - mn1);
            rs0 += s[nn][0] + s[nn][1];
            rs1 += s[nn][2] + s[nn][3];
        }
        rs0 += __shfl_xor_sync(0xffffffffu, rs0, 1);
        rs0 += __shfl_xor_sync(0xffffffffu, rs0, 2);
        rs1 += __shfl_xor_sync(0xffffffffu, rs1, 1);
        rs1 += __shfl_xor_sync(0xffffffffu, rs1, 2);
        l0 = l0 * corr0 + rs0; l1 = l1 * corr1 + rs1;
        m0 = mn0; m1 = mn1;
        #pragma unroll
        for (int nn = 0; nn < 8; nn++) {
            of[nn][0] *= corr0; of[nn][1] *= corr0;
            of[nn][2] *= corr1; of[nn][3] *= corr1;
        }

        // ---- O += P V ----
        #pragma unroll
        for (int kk = 0; kk < 4; kk++) {
            unsigned a0 = pk2(s[2 * kk][1],     s[2 * kk][0]);
            unsigned a1 = pk2(s[2 * kk][3],     s[2 * kk][2]);
            unsigned a2 = pk2(s[2 * kk + 1][1], s[2 * kk + 1][0]);
            unsigned a3 = pk2(s[2 * kk + 1][3], s[2 * kk + 1][2]);
            #pragma unroll
            for (int np = 0; np < 4; np++) {
                unsigned b0, b1, b2, b3;
                LDSM4(b0, b1, b2, b3, vb + (unsigned)((np * 16 * SSTR + kk * 16) * 2));
                MMA16816(of[2 * np],     a0, a1, a2, a3, b0, b1);
                MMA16816(of[2 * np + 1], a0, a1, a2, a3, b2, b3);
            }
        }
    }

    // ---- epilogue: res = (O/l) @ Wo + bo + xn ----
    __syncthreads();
    for (int i = tid; i < 512; i += 256) {
        int row = i >> 3, cc = i & 7;
        *(float4*)(Ks + row * SSTR + cc * 8) =
            *(const float4*)(g_woT + row * 64 + cc * 8);
    }
    __syncthreads();

    float inv0 = 1.f / l0, inv1 = 1.f / l1;
    #pragma unroll
    for (int nn = 0; nn < 8; nn++) {
        of[nn][0] *= inv0; of[nn][1] *= inv0;
        of[nn][2] *= inv1; of[nn][3] *= inv1;
    }

    float r[8][4];
    #pragma unroll
    for (int nn = 0; nn < 8; nn++)
        #pragma unroll
        for (int i = 0; i < 4; i++) r[nn][i] = 0.f;
    #pragma unroll
    for (int kk = 0; kk < 4; kk++) {
        unsigned a0 = pk2(of[2 * kk][1],     of[2 * kk][0]);
        unsigned a1 = pk2(of[2 * kk][3],     of[2 * kk][2]);
        unsigned a2 = pk2(of[2 * kk + 1][1], of[2 * kk + 1][0]);
        unsigned a3 = pk2(of[2 * kk + 1][3], of[2 * kk + 1][2]);
        #pragma unroll
        for (int np = 0; np < 4; np++) {
            unsigned b0, b1, b2, b3;
            LDSM4(b0, b1, b2, b3, kbase + boff + (unsigned)((np * 16 * SSTR + kk * 16) * 2));
            MMA16816(r[2 * np],     a0, a1, a2, a3, b0, b1);
            MMA16816(r[2 * np + 1], a0, a1, a2, a3, b2, b3);
        }
    }

    #pragma unroll
    for (int nn = 0; nn < 8; nn++) {
        int col = nn * 8 + c4 * 2;
        float2 bv = *(const float2*)(bo + col);
        size_t i0 = ((size_t)b * 4096 + t0 + qr + g) * 64 + col;
        float2 x0 = *(const float2*)(g_xn + i0);
        float2 o0 = make_float2(r[nn][0] + bv.x + x0.x, r[nn][1] + bv.y + x0.y);
        *(float2*)(out + i0) = o0;
        size_t i1 = i0 + (size_t)8 * 64;
        float2 x1 = *(const float2*)(g_xn + i1);
        float2 o1 = make_float2(r[nn][2] + bv.x + x1.x, r[nn][3] + bv.y + x1.y);
        *(float2*)(out + i1) = o1;
    }
}

// ---------------- launch ----------------------------------------------------
extern "C" void kernel_launch(void* const* d_in, const int* in_sizes, int n_in,
                              void* d_out, int out_size)
{
    const float* x     = (const float*)d_in[0];
    const float* gamma = (const float*)d_in[1];
    const float* beta  = (const float*)d_in[2];
    const float* Wq    = (const float*)d_in[3];
    const float* bq    = (const float*)d_in[4];
    const float* Wk    = (const float*)d_in[5];
    const float* bk    = (const float*)d_in[6];
    const float* Wv    = (const float*)d_in[7];
    const float* bv    = (const float*)d_in[8];
    const float* Wo    = (const float*)d_in[9];
    const float* bo    = (const float*)d_in[10];
    float* out = (float*)d_out;

    const int attn_smem = (128 * SSTR + 4 * 64 * SSTR) * 2;   // 55296 B
    cudaFuncSetAttribute(attn_kernel,
                         cudaFuncAttributeMaxDynamicSharedMemorySize, attn_smem);

    gn_stats_kernel<<<BATCH * GROUPS, 256>>>(x);
    wo_prep_kernel<<<1, 256>>>(Wo);
    gn_qkv_kernel<<<BATCH * 64, 256>>>(x, gamma, beta, Wq, bq, Wk, bk, Wv, bv);
    attn_kernel<<<BATCH * 32, 256, attn_smem>>>(bo, out);
}

// round 4
// speedup vs baseline: 5.5111x; 1.0784x over previous
#include <cuda_runtime.h>
#include <cuda_bf16.h>
#include <math_constants.h>

// Problem constants: B=4, H=64, W=64, C=64, GROUPS=8
#define BATCH 4
#define GROUPS 8
#define SEQ 4096
#define NTOK (BATCH * SEQ)
#define GN_EPS 1e-5f
#define SCALE 0.125f
#define LOG2E 1.4426950408889634f

// ---------------- scratch ---------------------------------------------------
__device__ float g_psum[256];
__device__ float g_psum2[256];
__device__ float g_xn[NTOK * 64];                        // fp32 [b][t][c]
__device__ __nv_bfloat16 g_qb[NTOK * 64];                // bf16 [b][t][d] (pre-scaled)
__device__ __nv_bfloat16 g_kb[NTOK * 64];                // bf16 [b][t][d]
__device__ __nv_bfloat16 g_vtb[BATCH * 64 * SEQ];        // bf16 [b][d][t]
__device__ __nv_bfloat16 g_woT[64 * 64];                 // bf16 [out][in]

// ---------------- PTX helpers ----------------------------------------------
#define LDSM4(r0, r1, r2, r3, addr)                                          \
    asm volatile("ldmatrix.sync.aligned.m8n8.x4.shared.b16 {%0,%1,%2,%3}, [%4];" \
                 : "=r"(r0), "=r"(r1), "=r"(r2), "=r"(r3) : "r"(addr))

#define MMA16816(d, a0, a1, a2, a3, b0, b1)                                  \
    asm volatile("mma.sync.aligned.m16n8k16.row.col.f32.bf16.bf16.f32 "      \
                 "{%0,%1,%2,%3}, {%4,%5,%6,%7}, {%8,%9}, {%0,%1,%2,%3};"     \
                 : "+f"(d[0]), "+f"(d[1]), "+f"(d[2]), "+f"(d[3])            \
                 : "r"(a0), "r"(a1), "r"(a2), "r"(a3), "r"(b0), "r"(b1))

#define CP_ASYNC16(dst, src)                                                 \
    asm volatile("cp.async.cg.shared.global [%0], [%1], 16;"                 \
                 :: "r"(dst), "l"(src))
#define CP_COMMIT()  asm volatile("cp.async.commit_group;")
#define CP_WAIT1()   asm volatile("cp.async.wait_group 1;")

__device__ __forceinline__ unsigned pk2(float hi, float lo) {
    unsigned d;
    asm("cvt.rn.bf16x2.f32 %0, %1, %2;" : "=r"(d) : "f"(hi), "f"(lo));
    return d;
}
__device__ __forceinline__ float ex2(float x) {
    float r;
    asm("ex2.approx.f32 %0, %1;" : "=f"(r) : "f"(x));
    return r;
}

// ---------------- kernel 1: partial GN sums + Wo transpose -------------------
// blocks 0..255: partial sums (8 chunks per (b,g) group). block 256: Wo^T.
__global__ void prep_kernel(const float* __restrict__ x,
                            const float* __restrict__ Wo) {
    if (blockIdx.x == 256) {
        for (int i = threadIdx.x; i < 4096; i += 256) {
            int o = i & 63, in = i >> 6;
            g_woT[o * 64 + in] = __float2bfloat16(Wo[in * 64 + o]);
        }
        return;
    }
    int blk = blockIdx.x;                 // bg*8 + chunk
    const float4* p = (const float4*)(x + (size_t)blk * 4096);
    float s = 0.f, s2 = 0.f;
    for (int i = threadIdx.x; i < 1024; i += 256) {
        float4 v = p[i];
        s  += v.x + v.y + v.z + v.w;
        s2 += v.x * v.x + v.y * v.y + v.z * v.z + v.w * v.w;
    }
    __shared__ float sh1[256], sh2[256];
    int tid = threadIdx.x;
    sh1[tid] = s; sh2[tid] = s2;
    __syncthreads();
    for (int st = 128; st > 0; st >>= 1) {
        if (tid < st) { sh1[tid] += sh1[tid + st]; sh2[tid] += sh2[tid + st]; }
        __syncthreads();
    }
    if (tid == 0) { g_psum[blk] = sh1[0]; g_psum2[blk] = sh2[0]; }
}

// ---------------- kernel 2: xn + Q/K/V projections --------------------------
__global__ void __launch_bounds__(256) gn_qkv_kernel(
    const float* __restrict__ x,
    const float* __restrict__ gamma, const float* __restrict__ beta,
    const float* __restrict__ Wq, const float* __restrict__ bq,
    const float* __restrict__ Wk, const float* __restrict__ bk,
    const float* __restrict__ Wv, const float* __restrict__ bv)
{
    __shared__ float xs[64 * 65];
    __shared__ float ws[64 * 64];

    int blk = blockIdx.x;             // b*64 + h
    int b = blk >> 6, h = blk & 63, gg = h >> 3;
    int tid = threadIdx.x;

    // reduce the 8 chunk partials of this group
    int base8 = (b * GROUPS + gg) * 8;
    float s = 0.f, s2 = 0.f;
    #pragma unroll
    for (int i = 0; i < 8; i++) { s += g_psum[base8 + i]; s2 += g_psum2[base8 + i]; }
    float mean = s * (1.f / 32768.f);
    float var  = s2 * (1.f / 32768.f) - mean * mean;
    float rstd = rsqrtf(var + GN_EPS);

    float a  = rstd * gamma[h];
    float c0 = beta[h] - mean * a;

    const float4* xp  = (const float4*)(x + (size_t)blk * 4096);
    float4*       xng = (float4*)(g_xn + (size_t)blk * 4096);

    for (int r = 0; r < 4; r++) {
        int i4 = tid + r * 256;
        float4 v = xp[i4];
        v.x = v.x * a + c0; v.y = v.y * a + c0;
        v.z = v.z * a + c0; v.w = v.w * a + c0;
        xng[i4] = v;
        int e = i4 * 4, w = e >> 6, c = e & 63;
        xs[w * 65 + c + 0] = v.x; xs[w * 65 + c + 1] = v.y;
        xs[w * 65 + c + 2] = v.z; xs[w * 65 + c + 3] = v.w;
    }
    __syncthreads();

    const float SC2 = SCALE * LOG2E;

    // ---- Q and K: token-major bf16; thread = (c, wb). Q pre-scaled by SC2 --
    for (int mtx = 0; mtx < 2; mtx++) {
        const float* Wm = mtx ? Wk : Wq;
        const float* bm = mtx ? bk : bq;
        __nv_bfloat16* og = mtx ? g_kb : g_qb;
        float qs = mtx ? 1.f : SC2;
        for (int r = 0; r < 4; r++)
            ((float4*)ws)[tid + r * 256] = ((const float4*)Wm)[tid + r * 256];
        __syncthreads();

        int c = tid & 63, wb = tid >> 6;
        float acc[16];
        #pragma unroll
        for (int i = 0; i < 16; i++) acc[i] = 0.f;
        for (int j = 0; j < 64; j++) {
            float wv = ws[j * 64 + c];
            #pragma unroll
            for (int i = 0; i < 16; i++)
                acc[i] += xs[(wb * 16 + i) * 65 + j] * wv;
        }
        float bb = bm[c];
        #pragma unroll
        for (int i = 0; i < 16; i++)
            og[((size_t)b * 4096 + h * 64 + wb * 16 + i) * 64 + c] =
                __float2bfloat16((acc[i] + bb) * qs);
        __syncthreads();
    }

    // ---- V: transposed [b][d][t] bf16; thread = (w, cb) --------------------
    for (int r = 0; r < 4; r++)
        ((float4*)ws)[tid + r * 256] = ((const float4*)Wv)[tid + r * 256];
    __syncthreads();
    {
        int w = tid & 63, cb = tid >> 6;
        float acc[16];
        #pragma unroll
        for (int c = 0; c < 16; c++) acc[c] = 0.f;
        for (int j = 0; j < 64; j++) {
            float xv = xs[w * 65 + j];
            const float* wr = ws + j * 64 + cb * 16;
            #pragma unroll
            for (int c = 0; c < 16; c++) acc[c] += xv * wr[c];
        }
        #pragma unroll
        for (int c = 0; c < 16; c++) {
            int cc = cb * 16 + c;
            g_vtb[(size_t)(b * 64 + cc) * 4096 + h * 64 + w] =
                __float2bfloat16(acc[c] + bv[cc]);
        }
    }
}

// ---------------- kernel 3: flash attention --------------------------------
// 256 threads = 8 warps, 128 queries. Key tiles of 64, 3-stage cp.async,
// fixed-max (M=0) log2-domain softmax, deferred row-sum reduction.
#define SSTR 72                    // smem row stride in bf16 (144B)
#define KVB  (64 * SSTR * 2)       // bytes per tile per array stage

__global__ void __launch_bounds__(256) attn_kernel(
    const float* __restrict__ bo, float* __restrict__ out)
{
    extern __shared__ __align__(16) __nv_bfloat16 dsm[];
    __nv_bfloat16* Qs  = dsm;                   // 128 x SSTR
    __nv_bfloat16* Ks  = Qs + 128 * SSTR;       // 3 stages x 64 x SSTR
    __nv_bfloat16* Vts = Ks + 3 * 64 * SSTR;    // 3 stages x 64 x SSTR

    int b = blockIdx.x >> 5, qt = blockIdx.x & 31;
    int t0 = qt * 128;
    int tid = threadIdx.x;
    int warp = tid >> 5, lane = tid & 31;
    int qr = warp * 16;
    int g = lane >> 2, c4 = lane & 3;

    const __nv_bfloat16* qg  = g_qb  + ((size_t)b * 4096 + t0) * 64;
    const __nv_bfloat16* kgb = g_kb  + (size_t)b * 4096 * 64;
    const __nv_bfloat16* vtg = g_vtb + (size_t)b * 64 * 4096;

    unsigned qbase = (unsigned)__cvta_generic_to_shared(Qs);
    unsigned kbase = (unsigned)__cvta_generic_to_shared(Ks);
    unsigned vbase = (unsigned)__cvta_generic_to_shared(Vts);

    int lrow0 = tid >> 3,          lcc0 = tid & 7;
    int lrow1 = (tid + 256) >> 3,  lcc1 = tid & 7;

    // prologue: Q + tile0 (G0), tile1 (G1)
    for (int i = tid; i < 1024; i += 256) {
        int row = i >> 3, cc = i & 7;
        CP_ASYNC16(qbase + (unsigned)((row * SSTR + cc * 8) * 2),
                   qg + row * 64 + cc * 8);
    }
    {
        CP_ASYNC16(kbase + (unsigned)((lrow0 * SSTR + lcc0 * 8) * 2), kgb + lrow0 * 64 + lcc0 * 8);
        CP_ASYNC16(kbase + (unsigned)((lrow1 * SSTR + lcc1 * 8) * 2), kgb + lrow1 * 64 + lcc1 * 8);
        CP_ASYNC16(vbase + (unsigned)((lrow0 * SSTR + lcc0 * 8) * 2), vtg + (size_t)lrow0 * 4096 + lcc0 * 8);
        CP_ASYNC16(vbase + (unsigned)((lrow1 * SSTR + lcc1 * 8) * 2), vtg + (size_t)lrow1 * 4096 + lcc1 * 8);
    }
    CP_COMMIT();   // G0
    {
        const __nv_bfloat16* kg = kgb + 64 * 64;
        const __nv_bfloat16* vg = vtg + 64;
        unsigned kd = kbase + KVB, vd = vbase + KVB;
        CP_ASYNC16(kd + (unsigned)((lrow0 * SSTR + lcc0 * 8) * 2), kg + lrow0 * 64 + lcc0 * 8);
        CP_ASYNC16(kd + (unsigned)((lrow1 * SSTR + lcc1 * 8) * 2), kg + lrow1 * 64 + lcc1 * 8);
        CP_ASYNC16(vd + (unsigned)((lrow0 * SSTR + lcc0 * 8) * 2), vg + (size_t)lrow0 * 4096 + lcc0 * 8);
        CP_ASYNC16(vd + (unsigned)((lrow1 * SSTR + lcc1 * 8) * 2), vg + (size_t)lrow1 * 4096 + lcc1 * 8);
    }
    CP_COMMIT();   // G1

    CP_WAIT1();    // G0 (Q + tile0) resident
    __syncthreads();

    int arow = (lane & 7) + (lane & 8);
    int acol = (lane >> 4) << 3;
    unsigned aaddr = qbase + (unsigned)(((qr + arow) * SSTR + acol) * 2);
    unsigned aQ[4][4];
    #pragma unroll
    for (int kk = 0; kk < 4; kk++)
        LDSM4(aQ[kk][0], aQ[kk][1], aQ[kk][2], aQ[kk][3], aaddr + kk * 32);

    unsigned boff = (unsigned)((((lane & 7) + ((lane & 16) >> 1)) * SSTR + (lane & 8)) * 2);

    float of[8][4];
    #pragma unroll
    for (int nn = 0; nn < 8; nn++)
        #pragma unroll
        for (int i = 0; i < 4; i++) of[nn][i] = 0.f;
    float l0 = 0.f, l1 = 0.f;

    int stc = 0;   // compute stage
    for (int kt = 0; kt < 64; kt++) {
        CP_WAIT1();        // tile kt resident
        __syncthreads();   // visible to all warps; all done with stage (kt-1)%3

        // prefetch tile kt+2 into stage (kt+2)%3
        if (kt + 2 < 64) {
            int sp = stc + 2; if (sp >= 3) sp -= 3;
            const __nv_bfloat16* kg = kgb + (size_t)(kt + 2) * 64 * 64;
            const __nv_bfloat16* vg = vtg + (size_t)(kt + 2) * 64;
            unsigned kd = kbase + (unsigned)(sp * KVB);
            unsigned vd = vbase + (unsigned)(sp * KVB);
            CP_ASYNC16(kd + (unsigned)((lrow0 * SSTR + lcc0 * 8) * 2), kg + lrow0 * 64 + lcc0 * 8);
            CP_ASYNC16(kd + (unsigned)((lrow1 * SSTR + lcc1 * 8) * 2), kg + lrow1 * 64 + lcc1 * 8);
            CP_ASYNC16(vd + (unsigned)((lrow0 * SSTR + lcc0 * 8) * 2), vg + (size_t)lrow0 * 4096 + lcc0 * 8);
            CP_ASYNC16(vd + (unsigned)((lrow1 * SSTR + lcc1 * 8) * 2), vg + (size_t)lrow1 * 4096 + lcc1 * 8);
        }
        CP_COMMIT();

        unsigned kb = kbase + (unsigned)(stc * KVB) + boff;
        unsigned vb = vbase + (unsigned)(stc * KVB) + boff;
        stc = (stc == 2) ? 0 : stc + 1;

        // ---- S = Q K^T (log2-domain: Q pre-scaled by SCALE*log2e) ----
        float s[8][4];
        #pragma unroll
        for (int nn = 0; nn < 8; nn++)
            #pragma unroll
            for (int i = 0; i < 4; i++) s[nn][i] = 0.f;
        #pragma unroll
        for (int kk = 0; kk < 4; kk++) {
            #pragma unroll
            for (int np = 0; np < 4; np++) {
                unsigned b0, b1, b2, b3;
                LDSM4(b0, b1, b2, b3, kb + (unsigned)((np * 16 * SSTR + kk * 16) * 2));
                MMA16816(s[2 * np],     aQ[kk][0], aQ[kk][1], aQ[kk][2], aQ[kk][3], b0, b1);
                MMA16816(s[2 * np + 1], aQ[kk][0], aQ[kk][1], aQ[kk][2], aQ[kk][3], b2, b3);
            }
        }

        // ---- fixed-max softmax: p = 2^s; accumulate row-sums per lane ----
        #pragma unroll
        for (int nn = 0; nn < 8; nn++) {
            s[nn][0] = ex2(s[nn][0]);
            s[nn][1] = ex2(s[nn][1]);
            s[nn][2] = ex2(s[nn][2]);
            s[nn][3] = ex2(s[nn][3]);
            l0 += s[nn][0] + s[nn][1];
            l1 += s[nn][2] + s[nn][3];
        }

        // ---- O += P V ----
        #pragma unroll
        for (int kk = 0; kk < 4; kk++) {
            unsigned a0 = pk2(s[2 * kk][1],     s[2 * kk][0]);
            unsigned a1 = pk2(s[2 * kk][3],     s[2 * kk][2]);
            unsigned a2 = pk2(s[2 * kk + 1][1], s[2 * kk + 1][0]);
            unsigned a3 = pk2(s[2 * kk + 1][3], s[2 * kk + 1][2]);
            #pragma unroll
            for (int np = 0; np < 4; np++) {
                unsigned b0, b1, b2, b3;
                LDSM4(b0, b1, b2, b3, vb + (unsigned)((np * 16 * SSTR + kk * 16) * 2));
                MMA16816(of[2 * np],     a0, a1, a2, a3, b0, b1);
                MMA16816(of[2 * np + 1], a0, a1, a2, a3, b2, b3);
            }
        }
    }

    // ---- deferred row-sum reduction over quad ----
    l0 += __shfl_xor_sync(0xffffffffu, l0, 1);
    l0 += __shfl_xor_sync(0xffffffffu, l0, 2);
    l1 += __shfl_xor_sync(0xffffffffu, l1, 1);
    l1 += __shfl_xor_sync(0xffffffffu, l1, 2);

    // ---- epilogue: res = (O/l) @ Wo + bo + xn ----
    __syncthreads();
    for (int i = tid; i < 512; i += 256) {
        int row = i >> 3, cc = i & 7;
        *(float4*)(Ks + row * SSTR + cc * 8) =
            *(const float4*)(g_woT + row * 64 + cc * 8);
    }
    __syncthreads();

    float inv0 = 1.f / l0, inv1 = 1.f / l1;
    #pragma unroll
    for (int nn = 0; nn < 8; nn++) {
        of[nn][0] *= inv0; of[nn][1] *= inv0;
        of[nn][2] *= inv1; of[nn][3] *= inv1;
    }

    float r[8][4];
    #pragma unroll
    for (int nn = 0; nn < 8; nn++)
        #pragma unroll
        for (int i = 0; i < 4; i++) r[nn][i] = 0.f;
    #pragma unroll
    for (int kk = 0; kk < 4; kk++) {
        unsigned a0 = pk2(of[2 * kk][1],     of[2 * kk][0]);
        unsigned a1 = pk2(of[2 * kk][3],     of[2 * kk][2]);
        unsigned a2 = pk2(of[2 * kk + 1][1], of[2 * kk + 1][0]);
        unsigned a3 = pk2(of[2 * kk + 1][3], of[2 * kk + 1][2]);
        #pragma unroll
        for (int np = 0; np < 4; np++) {
            unsigned b0, b1, b2, b3;
            LDSM4(b0, b1, b2, b3, kbase + boff + (unsigned)((np * 16 * SSTR + kk * 16) * 2));
            MMA16816(r[2 * np],     a0, a1, a2, a3, b0, b1);
            MMA16816(r[2 * np + 1], a0, a1, a2, a3, b2, b3);
        }
    }

    #pragma unroll
    for (int nn = 0; nn < 8; nn++) {
        int col = nn * 8 + c4 * 2;
        float2 bv = *(const float2*)(bo + col);
        size_t i0 = ((size_t)b * 4096 + t0 + qr + g) * 64 + col;
        float2 x0 = *(const float2*)(g_xn + i0);
        float2 o0 = make_float2(r[nn][0] + bv.x + x0.x, r[nn][1] + bv.y + x0.y);
        *(float2*)(out + i0) = o0;
        size_t i1 = i0 + (size_t)8 * 64;
        float2 x1 = *(const float2*)(g_xn + i1);
        float2 o1 = make_float2(r[nn][2] + bv.x + x1.x, r[nn][3] + bv.y + x1.y);
        *(float2*)(out + i1) = o1;
    }
}

// ---------------- launch ----------------------------------------------------
extern "C" void kernel_launch(void* const* d_in, const int* in_sizes, int n_in,
                              void* d_out, int out_size)
{
    const float* x     = (const float*)d_in[0];
    const float* gamma = (const float*)d_in[1];
    const float* beta  = (const float*)d_in[2];
    const float* Wq    = (const float*)d_in[3];
    const float* bq    = (const float*)d_in[4];
    const float* Wk    = (const float*)d_in[5];
    const float* bk    = (const float*)d_in[6];
    const float* Wv    = (const float*)d_in[7];
    const float* bv    = (const float*)d_in[8];
    const float* Wo    = (const float*)d_in[9];
    const float* bo    = (const float*)d_in[10];
    float* out = (float*)d_out;

    const int attn_smem = (128 * SSTR + 6 * 64 * SSTR) * 2;   // 73728 B
    cudaFuncSetAttribute(attn_kernel,
                         cudaFuncAttributeMaxDynamicSharedMemorySize, attn_smem);

    prep_kernel<<<257, 256>>>(x, Wo);
    gn_qkv_kernel<<<BATCH * 64, 256>>>(x, gamma, beta, Wq, bq, Wk, bk, Wv, bv);
    attn_kernel<<<BATCH * 32, 256, attn_smem>>>(bo, out);
}

// round 6
// speedup vs baseline: 6.8218x; 1.2378x over previous
#include <cuda_runtime.h>
#include <cuda_bf16.h>
#include <math_constants.h>

// Problem constants: B=4, H=64, W=64, C=64, GROUPS=8
#define BATCH 4
#define GROUPS 8
#define SEQ 4096
#define NTOK (BATCH * SEQ)
#define GN_EPS 1e-5f
#define SCALE 0.125f
#define LOG2E 1.4426950408889634f

// ---------------- scratch ---------------------------------------------------
__device__ float g_psum[128];
__device__ float g_psum2[128];
__device__ float g_xn[NTOK * 64];                        // fp32 [b][t][c]
__device__ __nv_bfloat16 g_qb[NTOK * 64];                // bf16 [b][t][d] (pre-scaled)
__device__ __nv_bfloat16 g_kb[NTOK * 64];                // bf16 [b][t][d]
__device__ __nv_bfloat16 g_vtb[BATCH * 64 * SEQ];        // bf16 [b][d][t]
__device__ __nv_bfloat16 g_woT[64 * 64];                 // bf16 [out][in]

// ---------------- PTX helpers ----------------------------------------------
#define LDSM4(r0, r1, r2, r3, addr)                                          \
    asm volatile("ldmatrix.sync.aligned.m8n8.x4.shared.b16 {%0,%1,%2,%3}, [%4];" \
                 : "=r"(r0), "=r"(r1), "=r"(r2), "=r"(r3) : "r"(addr))

#define MMA16816(d, a0, a1, a2, a3, b0, b1)                                  \
    asm volatile("mma.sync.aligned.m16n8k16.row.col.f32.bf16.bf16.f32 "      \
                 "{%0,%1,%2,%3}, {%4,%5,%6,%7}, {%8,%9}, {%0,%1,%2,%3};"     \
                 : "+f"(d[0]), "+f"(d[1]), "+f"(d[2]), "+f"(d[3])            \
                 : "r"(a0), "r"(a1), "r"(a2), "r"(a3), "r"(b0), "r"(b1))

#define CP_ASYNC16(dst, src)                                                 \
    asm volatile("cp.async.cg.shared.global [%0], [%1], 16;"                 \
                 :: "r"(dst), "l"(src))
#define CP_COMMIT()  asm volatile("cp.async.commit_group;")
#define CP_WAIT1()   asm volatile("cp.async.wait_group 1;")

#define GROUP_BAR(id)                                                        \
    asm volatile("bar.sync %0, %1;" :: "r"(id), "r"(256) : "memory")

__device__ __forceinline__ unsigned pk2(float hi, float lo) {
    unsigned d;
    asm("cvt.rn.bf16x2.f32 %0, %1, %2;" : "=r"(d) : "f"(hi), "f"(lo));
    return d;
}
__device__ __forceinline__ float ex2(float x) {
    float r;
    asm("ex2.approx.f32 %0, %1;" : "=f"(r) : "f"(x));
    return r;
}

// ---------------- kernel 1: partial GN sums + Wo transpose -------------------
// blocks 0..127: partial sums (4 chunks per (b,g) group, MLP=8). block 128: Wo^T.
__global__ void prep_kernel(const float* __restrict__ x,
                            const float* __restrict__ Wo) {
    if (blockIdx.x == 128) {
        for (int i = threadIdx.x; i < 4096; i += 256) {
            int o = i & 63, in = i >> 6;
            g_woT[o * 64 + in] = __float2bfloat16(Wo[in * 64 + o]);
        }
        return;
    }
    int blk = blockIdx.x;                  // bg*4 + chunk
    const float4* p = (const float4*)(x + (size_t)blk * 8192);
    int tid = threadIdx.x;
    float s = 0.f, s2 = 0.f;
    #pragma unroll
    for (int j = 0; j < 8; j++) {
        float4 v = p[tid + j * 256];
        s  += v.x + v.y + v.z + v.w;
        s2 += v.x * v.x + v.y * v.y + v.z * v.z + v.w * v.w;
    }
    __shared__ float sh1[256], sh2[256];
    sh1[tid] = s; sh2[tid] = s2;
    __syncthreads();
    for (int st = 128; st > 0; st >>= 1) {
        if (tid < st) { sh1[tid] += sh1[tid + st]; sh2[tid] += sh2[tid + st]; }
        __syncthreads();
    }
    if (tid == 0) { g_psum[blk] = sh1[0]; g_psum2[blk] = sh2[0]; }
}

// ---------------- kernel 2: xn + Q/K/V projections --------------------------
__global__ void __launch_bounds__(256) gn_qkv_kernel(
    const float* __restrict__ x,
    const float* __restrict__ gamma, const float* __restrict__ beta,
    const float* __restrict__ Wq, const float* __restrict__ bq,
    const float* __restrict__ Wk, const float* __restrict__ bk,
    const float* __restrict__ Wv, const float* __restrict__ bv)
{
    __shared__ float xs[64 * 65];
    __shared__ float ws[64 * 64];

    int blk = blockIdx.x;             // b*64 + h
    int b = blk >> 6, h = blk & 63, gg = h >> 3;
    int tid = threadIdx.x;

    int base4 = (b * GROUPS + gg) * 4;
    float s = 0.f, s2 = 0.f;
    #pragma unroll
    for (int i = 0; i < 4; i++) { s += g_psum[base4 + i]; s2 += g_psum2[base4 + i]; }
    float mean = s * (1.f / 32768.f);
    float var  = s2 * (1.f / 32768.f) - mean * mean;
    float rstd = rsqrtf(var + GN_EPS);

    float a  = rstd * gamma[h];
    float c0 = beta[h] - mean * a;

    const float4* xp  = (const float4*)(x + (size_t)blk * 4096);
    float4*       xng = (float4*)(g_xn + (size_t)blk * 4096);

    for (int r = 0; r < 4; r++) {
        int i4 = tid + r * 256;
        float4 v = xp[i4];
        v.x = v.x * a + c0; v.y = v.y * a + c0;
        v.z = v.z * a + c0; v.w = v.w * a + c0;
        xng[i4] = v;
        int e = i4 * 4, w = e >> 6, c = e & 63;
        xs[w * 65 + c + 0] = v.x; xs[w * 65 + c + 1] = v.y;
        xs[w * 65 + c + 2] = v.z; xs[w * 65 + c + 3] = v.w;
    }
    __syncthreads();

    const float SC2 = SCALE * LOG2E;

    // ---- Q and K: token-major bf16; thread = (c, wb). Q pre-scaled by SC2 --
    for (int mtx = 0; mtx < 2; mtx++) {
        const float* Wm = mtx ? Wk : Wq;
        const float* bm = mtx ? bk : bq;
        __nv_bfloat16* og = mtx ? g_kb : g_qb;
        float qs = mtx ? 1.f : SC2;
        for (int r = 0; r < 4; r++)
            ((float4*)ws)[tid + r * 256] = ((const float4*)Wm)[tid + r * 256];
        __syncthreads();

        int c = tid & 63, wb = tid >> 6;
        float acc[16];
        #pragma unroll
        for (int i = 0; i < 16; i++) acc[i] = 0.f;
        for (int j = 0; j < 64; j++) {
            float wv = ws[j * 64 + c];
            #pragma unroll
            for (int i = 0; i < 16; i++)
                acc[i] += xs[(wb * 16 + i) * 65 + j] * wv;
        }
        float bb = bm[c];
        #pragma unroll
        for (int i = 0; i < 16; i++)
            og[((size_t)b * 4096 + h * 64 + wb * 16 + i) * 64 + c] =
                __float2bfloat16((acc[i] + bb) * qs);
        __syncthreads();
    }

    // ---- V: transposed [b][d][t] bf16; thread = (w, cb) --------------------
    for (int r = 0; r < 4; r++)
        ((float4*)ws)[tid + r * 256] = ((const float4*)Wv)[tid + r * 256];
    __syncthreads();
    {
        int w = tid & 63, cb = tid >> 6;
        float acc[16];
        #pragma unroll
        for (int c = 0; c < 16; c++) acc[c] = 0.f;
        for (int j = 0; j < 64; j++) {
            float xv = xs[w * 65 + j];
            const float* wr = ws + j * 64 + cb * 16;
            #pragma unroll
            for (int c = 0; c < 16; c++) acc[c] += xv * wr[c];
        }
        #pragma unroll
        for (int c = 0; c < 16; c++) {
            int cc = cb * 16 + c;
            g_vtb[(size_t)(b * 64 + cc) * 4096 + h * 64 + w] =
                __float2bfloat16(acc[c] + bv[cc]);
        }
    }
}

// ---------------- kernel 3: split-K flash attention -------------------------
// 512 threads = 16 warps. Warp-group A (warps 0-7): key tiles 0-31;
// group B (warps 8-15): tiles 32-63. Private 3-stage cp.async pipelines,
// per-group named barriers. Fixed-max log2 softmax => partials combine by
// simple addition at the end.
#define SSTR 72                    // smem row stride in bf16 (144B)
#define TILEE (64 * SSTR)          // bf16 elements per tile array

__global__ void __launch_bounds__(512, 1) attn_kernel(
    const float* __restrict__ bo, float* __restrict__ out)
{
    extern __shared__ __align__(16) __nv_bfloat16 dsm[];
    __nv_bfloat16* Qs = dsm;                        // 128 x SSTR (later: WoT)
    __nv_bfloat16* Kv = Qs + 128 * SSTR;            // [grp]{K:3 stages, V:3 stages}

    int b = blockIdx.x >> 5, qt = blockIdx.x & 31;
    int t0 = qt * 128;
    int tid = threadIdx.x;
    int warp = tid >> 5, lane = tid & 31;
    int grp = warp >> 3, warpg = warp & 7;
    int tidg = tid & 255;
    int qr = warpg * 16;
    int g = lane >> 2, c4 = lane & 3;
    int kt0 = grp * 32;

    const __nv_bfloat16* qg  = g_qb  + ((size_t)b * 4096 + t0) * 64;
    const __nv_bfloat16* kgb = g_kb  + (size_t)b * 4096 * 64;
    const __nv_bfloat16* vtg = g_vtb + (size_t)b * 64 * 4096;

    __nv_bfloat16* Kg = Kv + grp * 6 * TILEE;
    __nv_bfloat16* Vg = Kg + 3 * TILEE;

    unsigned qbase  = (unsigned)__cvta_generic_to_shared(Qs);
    unsigned kgbase = (unsigned)__cvta_generic_to_shared(Kg);
    unsigned vgbase = (unsigned)__cvta_generic_to_shared(Vg);

    int lrow0 = tidg >> 3,          lcc0 = tidg & 7;
    int lrow1 = (tidg + 256) >> 3,  lcc1 = tidg & 7;

    // ---- prologue: Q (all threads) + tiles kt0, kt0+1 (per group) ----------
    for (int i = tid; i < 1024; i += 512) {
        int row = i >> 3, cc = i & 7;
        CP_ASYNC16(qbase + (unsigned)((row * SSTR + cc * 8) * 2),
                   qg + row * 64 + cc * 8);
    }
    {
        const __nv_bfloat16* kg = kgb + (size_t)kt0 * 64 * 64;
        const __nv_bfloat16* vg = vtg + (size_t)kt0 * 64;
        CP_ASYNC16(kgbase + (unsigned)((lrow0 * SSTR + lcc0 * 8) * 2), kg + lrow0 * 64 + lcc0 * 8);
        CP_ASYNC16(kgbase + (unsigned)((lrow1 * SSTR + lcc1 * 8) * 2), kg + lrow1 * 64 + lcc1 * 8);
        CP_ASYNC16(vgbase + (unsigned)((lrow0 * SSTR + lcc0 * 8) * 2), vg + (size_t)lrow0 * 4096 + lcc0 * 8);
        CP_ASYNC16(vgbase + (unsigned)((lrow1 * SSTR + lcc1 * 8) * 2), vg + (size_t)lrow1 * 4096 + lcc1 * 8);
    }
    CP_COMMIT();   // G0: Q + tile kt0
    {
        const __nv_bfloat16* kg = kgb + (size_t)(kt0 + 1) * 64 * 64;
        const __nv_bfloat16* vg = vtg + (size_t)(kt0 + 1) * 64;
        unsigned kd = kgbase + TILEE * 2, vd = vgbase + TILEE * 2;
        CP_ASYNC16(kd + (unsigned)((lrow0 * SSTR + lcc0 * 8) * 2), kg + lrow0 * 64 + lcc0 * 8);
        CP_ASYNC16(kd + (unsigned)((lrow1 * SSTR + lcc1 * 8) * 2), kg + lrow1 * 64 + lcc1 * 8);
        CP_ASYNC16(vd + (unsigned)((lrow0 * SSTR + lcc0 * 8) * 2), vg + (size_t)lrow0 * 4096 + lcc0 * 8);
        CP_ASYNC16(vd + (unsigned)((lrow1 * SSTR + lcc1 * 8) * 2), vg + (size_t)lrow1 * 4096 + lcc1 * 8);
    }
    CP_COMMIT();   // G1: tile kt0+1

    CP_WAIT1();    // Q + tile kt0 resident (per-thread)
    __syncthreads();

    int arow = (lane & 7) + (lane & 8);
    int acol = (lane >> 4) << 3;
    unsigned aaddr = qbase + (unsigned)(((qr + arow) * SSTR + acol) * 2);
    unsigned aQ[4][4];
    #pragma unroll
    for (int kk = 0; kk < 4; kk++)
        LDSM4(aQ[kk][0], aQ[kk][1], aQ[kk][2], aQ[kk][3], aaddr + kk * 32);

    unsigned boff = (unsigned)((((lane & 7) + ((lane & 16) >> 1)) * SSTR + (lane & 8)) * 2);

    float of[8][4];
    #pragma unroll
    for (int nn = 0; nn < 8; nn++)
        #pragma unroll
        for (int i = 0; i < 4; i++) of[nn][i] = 0.f;
    float l0 = 0.f, l1 = 0.f;

    int stc = 0;
    for (int it = 0; it < 32; it++) {
        CP_WAIT1();          // tile kt0+it resident
        GROUP_BAR(grp + 1);  // group-wide: visible + prev compute done

        if (it + 2 < 32) {
            int sp = stc + 2; if (sp >= 3) sp -= 3;
            const __nv_bfloat16* kg = kgb + (size_t)(kt0 + it + 2) * 64 * 64;
            const __nv_bfloat16* vg = vtg + (size_t)(kt0 + it + 2) * 64;
            unsigned kd = kgbase + (unsigned)(sp * TILEE * 2);
            unsigned vd = vgbase + (unsigned)(sp * TILEE * 2);
            CP_ASYNC16(kd + (unsigned)((lrow0 * SSTR + lcc0 * 8) * 2), kg + lrow0 * 64 + lcc0 * 8);
            CP_ASYNC16(kd + (unsigned)((lrow1 * SSTR + lcc1 * 8) * 2), kg + lrow1 * 64 + lcc1 * 8);
            CP_ASYNC16(vd + (unsigned)((lrow0 * SSTR + lcc0 * 8) * 2), vg + (size_t)lrow0 * 4096 + lcc0 * 8);
            CP_ASYNC16(vd + (unsigned)((lrow1 * SSTR + lcc1 * 8) * 2), vg + (size_t)lrow1 * 4096 + lcc1 * 8);
        }
        CP_COMMIT();

        unsigned kb = kgbase + (unsigned)(stc * TILEE * 2) + boff;
        unsigned vb = vgbase + (unsigned)(stc * TILEE * 2) + boff;
        stc = (stc == 2) ? 0 : stc + 1;

        // ---- S = Q K^T (log2 domain, Q pre-scaled) ----
        float s[8][4];
        #pragma unroll
        for (int nn = 0; nn < 8; nn++)
            #pragma unroll
            for (int i = 0; i < 4; i++) s[nn][i] = 0.f;
        #pragma unroll
        for (int kk = 0; kk < 4; kk++) {
            #pragma unroll
            for (int np = 0; np < 4; np++) {
                unsigned b0, b1, b2, b3;
                LDSM4(b0, b1, b2, b3, kb + (unsigned)((np * 16 * SSTR + kk * 16) * 2));
                MMA16816(s[2 * np],     aQ[kk][0], aQ[kk][1], aQ[kk][2], aQ[kk][3], b0, b1);
                MMA16816(s[2 * np + 1], aQ[kk][0], aQ[kk][1], aQ[kk][2], aQ[kk][3], b2, b3);
            }
        }

        // ---- fixed-max softmax: p = 2^s ----
        #pragma unroll
        for (int nn = 0; nn < 8; nn++) {
            s[nn][0] = ex2(s[nn][0]);
            s[nn][1] = ex2(s[nn][1]);
            s[nn][2] = ex2(s[nn][2]);
            s[nn][3] = ex2(s[nn][3]);
            l0 += s[nn][0] + s[nn][1];
            l1 += s[nn][2] + s[nn][3];
        }

        // ---- O += P V ----
        #pragma unroll
        for (int kk = 0; kk < 4; kk++) {
            unsigned a0 = pk2(s[2 * kk][1],     s[2 * kk][0]);
            unsigned a1 = pk2(s[2 * kk][3],     s[2 * kk][2]);
            unsigned a2 = pk2(s[2 * kk + 1][1], s[2 * kk + 1][0]);
            unsigned a3 = pk2(s[2 * kk + 1][3], s[2 * kk + 1][2]);
            #pragma unroll
            for (int np = 0; np < 4; np++) {
                unsigned b0, b1, b2, b3;
                LDSM4(b0, b1, b2, b3, vb + (unsigned)((np * 16 * SSTR + kk * 16) * 2));
                MMA16816(of[2 * np],     a0, a1, a2, a3, b0, b1);
                MMA16816(of[2 * np + 1], a0, a1, a2, a3, b2, b3);
            }
        }
    }

    // ---- combine split-K partials (exchange via group-B smem area) ---------
    __syncthreads();
    float* ex = (float*)(Kv + 6 * TILEE);   // 256 lanes x 35 floats = 35840 B
    if (grp == 1) {
        float* pp = ex + (warpg * 32 + lane) * 35;
        #pragma unroll
        for (int nn = 0; nn < 8; nn++)
            #pragma unroll
            for (int i = 0; i < 4; i++) pp[nn * 4 + i] = of[nn][i];
        pp[32] = l0; pp[33] = l1;
    }
    __syncthreads();
    if (grp == 1) return;

    {
        float* pp = ex + (warpg * 32 + lane) * 35;
        #pragma unroll
        for (int nn = 0; nn < 8; nn++)
            #pragma unroll
            for (int i = 0; i < 4; i++) of[nn][i] += pp[nn * 4 + i];
        l0 += pp[32]; l1 += pp[33];
    }
    l0 += __shfl_xor_sync(0xffffffffu, l0, 1);
    l0 += __shfl_xor_sync(0xffffffffu, l0, 2);
    l1 += __shfl_xor_sync(0xffffffffu, l1, 1);
    l1 += __shfl_xor_sync(0xffffffffu, l1, 2);

    // ---- epilogue (group A only): res = (O/l) @ Wo + bo + xn ---------------
    for (int i = tidg; i < 512; i += 256) {
        int row = i >> 3, cc = i & 7;
        *(float4*)(Qs + row * SSTR + cc * 8) =
            *(const float4*)(g_woT + row * 64 + cc * 8);
    }
    GROUP_BAR(1);

    float inv0 = 1.f / l0, inv1 = 1.f / l1;
    #pragma unroll
    for (int nn = 0; nn < 8; nn++) {
        of[nn][0] *= inv0; of[nn][1] *= inv0;
        of[nn][2] *= inv1; of[nn][3] *= inv1;
    }

    float r[8][4];
    #pragma unroll
    for (int nn = 0; nn < 8; nn++)
        #pragma unroll
        for (int i = 0; i < 4; i++) r[nn][i] = 0.f;
    #pragma unroll
    for (int kk = 0; kk < 4; kk++) {
        unsigned a0 = pk2(of[2 * kk][1],     of[2 * kk][0]);
        unsigned a1 = pk2(of[2 * kk][3],     of[2 * kk][2]);
        unsigned a2 = pk2(of[2 * kk + 1][1], of[2 * kk + 1][0]);
        unsigned a3 = pk2(of[2 * kk + 1][3], of[2 * kk + 1][2]);
        #pragma unroll
        for (int np = 0; np < 4; np++) {
            unsigned b0, b1, b2, b3;
            LDSM4(b0, b1, b2, b3, qbase + boff + (unsigned)((np * 16 * SSTR + kk * 16) * 2));
            MMA16816(r[2 * np],     a0, a1, a2, a3, b0, b1);
            MMA16816(r[2 * np + 1], a0, a1, a2, a3, b2, b3);
        }
    }

    #pragma unroll
    for (int nn = 0; nn < 8; nn++) {
        int col = nn * 8 + c4 * 2;
        float2 bv = *(const float2*)(bo + col);
        size_t i0 = ((size_t)b * 4096 + t0 + qr + g) * 64 + col;
        float2 x0 = *(const float2*)(g_xn + i0);
        float2 o0 = make_float2(r[nn][0] + bv.x + x0.x, r[nn][1] + bv.y + x0.y);
        *(float2*)(out + i0) = o0;
        size_t i1 = i0 + (size_t)8 * 64;
        float2 x1 = *(const float2*)(g_xn + i1);
        float2 o1 = make_float2(r[nn][2] + bv.x + x1.x, r[nn][3] + bv.y + x1.y);
        *(float2*)(out + i1) = o1;
    }
}

// ---------------- launch ----------------------------------------------------
extern "C" void kernel_launch(void* const* d_in, const int* in_sizes, int n_in,
                              void* d_out, int out_size)
{
    const float* x     = (const float*)d_in[0];
    const float* gamma = (const float*)d_in[1];
    const float* beta  = (const float*)d_in[2];
    const float* Wq    = (const float*)d_in[3];
    const float* bq    = (const float*)d_in[4];
    const float* Wk    = (const float*)d_in[5];
    const float* bk    = (const float*)d_in[6];
    const float* Wv    = (const float*)d_in[7];
    const float* bv    = (const float*)d_in[8];
    const float* Wo    = (const float*)d_in[9];
    const float* bo    = (const float*)d_in[10];
    float* out = (float*)d_out;

    const int attn_smem = (128 * SSTR + 12 * 64 * SSTR) * 2;   // 129024 B
    cudaFuncSetAttribute(attn_kernel,
                         cudaFuncAttributeMaxDynamicSharedMemorySize, attn_smem);

    prep_kernel<<<129, 256>>>(x, Wo);
    gn_qkv_kernel<<<BATCH * 64, 256>>>(x, gamma, beta, Wq, bq, Wk, bk, Wv, bv);
    attn_kernel<<<BATCH * 32, 512, attn_smem>>>(bo, out);
}

// round 7
// speedup vs baseline: 6.8451x; 1.0034x over previous
#include <cuda_runtime.h>
#include <cuda_bf16.h>
#include <math_constants.h>

// Problem constants: B=4, H=64, W=64, C=64, GROUPS=8
#define BATCH 4
#define GROUPS 8
#define SEQ 4096
#define NTOK (BATCH * SEQ)
#define GN_EPS 1e-5f
#define SCALE 0.125f
#define LOG2E 1.4426950408889634f

// ---------------- scratch ---------------------------------------------------
__device__ float g_xn[NTOK * 64];                        // fp32 [b][t][c]
__device__ __nv_bfloat16 g_qb[NTOK * 64];                // bf16 [b][t][d] (pre-scaled)
__device__ __nv_bfloat16 g_kb[NTOK * 64];                // bf16 [b][t][d]
__device__ __nv_bfloat16 g_vtb[BATCH * 64 * SEQ];        // bf16 [b][d][t]
__device__ __nv_bfloat16 g_woT[64 * 64];                 // bf16 [out][in]

// ---------------- PTX helpers ----------------------------------------------
#define LDSM4(r0, r1, r2, r3, addr)                                          \
    asm volatile("ldmatrix.sync.aligned.m8n8.x4.shared.b16 {%0,%1,%2,%3}, [%4];" \
                 : "=r"(r0), "=r"(r1), "=r"(r2), "=r"(r3) : "r"(addr))

#define MMA16816(d, a0, a1, a2, a3, b0, b1)                                  \
    asm volatile("mma.sync.aligned.m16n8k16.row.col.f32.bf16.bf16.f32 "      \
                 "{%0,%1,%2,%3}, {%4,%5,%6,%7}, {%8,%9}, {%0,%1,%2,%3};"     \
                 : "+f"(d[0]), "+f"(d[1]), "+f"(d[2]), "+f"(d[3])            \
                 : "r"(a0), "r"(a1), "r"(a2), "r"(a3), "r"(b0), "r"(b1))

#define CP_ASYNC16(dst, src)                                                 \
    asm volatile("cp.async.cg.shared.global [%0], [%1], 16;"                 \
                 :: "r"(dst), "l"(src))
#define CP_COMMIT()  asm volatile("cp.async.commit_group;")
#define CP_WAIT1()   asm volatile("cp.async.wait_group 1;")

#define GROUP_BAR(id)                                                        \
    asm volatile("bar.sync %0, %1;" :: "r"(id), "r"(256) : "memory")

__device__ __forceinline__ unsigned pk2(float hi, float lo) {
    unsigned d;
    asm("cvt.rn.bf16x2.f32 %0, %1, %2;" : "=r"(d) : "f"(hi), "f"(lo));
    return d;
}
__device__ __forceinline__ float ex2(float x) {
    float r;
    asm("ex2.approx.f32 %0, %1;" : "=f"(r) : "f"(x));
    return r;
}

// ---------------- kernel 1: fused GN stats + xn + Q/K/V (+WoT) --------------
// One block per (b,h). Each block redundantly reduces its own group's
// 32768 floats (L2-resident across the 8 sibling blocks), then projects.
__global__ void __launch_bounds__(256) gn_qkv_kernel(
    const float* __restrict__ x,
    const float* __restrict__ gamma, const float* __restrict__ beta,
    const float* __restrict__ Wq, const float* __restrict__ bq,
    const float* __restrict__ Wk, const float* __restrict__ bk,
    const float* __restrict__ Wv, const float* __restrict__ bv,
    const float* __restrict__ Wo)
{
    __shared__ float xs[64 * 65];
    __shared__ float ws[64 * 64];

    int blk = blockIdx.x;             // b*64 + h
    int b = blk >> 6, h = blk & 63, gg = h >> 3;
    int tid = threadIdx.x;

    // ---- group statistics (this block's group: 8 h-rows = 32768 floats) ----
    const float4* gp = (const float4*)(x + (size_t)(b * 64 + gg * 8) * 4096);
    float s = 0.f, s2 = 0.f;
    #pragma unroll 8
    for (int i = tid; i < 8192; i += 256) {
        float4 v = gp[i];
        s  += v.x + v.y + v.z + v.w;
        s2 += v.x * v.x + v.y * v.y + v.z * v.z + v.w * v.w;
    }
    float* sh1 = ws;            // scratch before ws holds weights
    float* sh2 = ws + 256;
    sh1[tid] = s; sh2[tid] = s2;
    __syncthreads();
    for (int st = 128; st > 0; st >>= 1) {
        if (tid < st) { sh1[tid] += sh1[tid + st]; sh2[tid] += sh2[tid + st]; }
        __syncthreads();
    }
    if (tid == 0) {
        float mean = sh1[0] * (1.f / 32768.f);
        float var  = sh2[0] * (1.f / 32768.f) - mean * mean;
        xs[0] = mean;
        xs[1] = rsqrtf(var + GN_EPS);
    }
    __syncthreads();
    float mean = xs[0], rstd = xs[1];
    __syncthreads();            // xs[0..1] consumed before xs refilled below

    float a  = rstd * gamma[h];
    float c0 = beta[h] - mean * a;

    const float4* xp  = (const float4*)(x + (size_t)blk * 4096);
    float4*       xng = (float4*)(g_xn + (size_t)blk * 4096);

    for (int r = 0; r < 4; r++) {
        int i4 = tid + r * 256;
        float4 v = xp[i4];
        v.x = v.x * a + c0; v.y = v.y * a + c0;
        v.z = v.z * a + c0; v.w = v.w * a + c0;
        xng[i4] = v;
        int e = i4 * 4, w = e >> 6, c = e & 63;
        xs[w * 65 + c + 0] = v.x; xs[w * 65 + c + 1] = v.y;
        xs[w * 65 + c + 2] = v.z; xs[w * 65 + c + 3] = v.w;
    }
    __syncthreads();

    const float SC2 = SCALE * LOG2E;

    // ---- Q and K: token-major bf16; thread = (c, wb). Q pre-scaled by SC2 --
    for (int mtx = 0; mtx < 2; mtx++) {
        const float* Wm = mtx ? Wk : Wq;
        const float* bm = mtx ? bk : bq;
        __nv_bfloat16* og = mtx ? g_kb : g_qb;
        float qs = mtx ? 1.f : SC2;
        for (int r = 0; r < 4; r++)
            ((float4*)ws)[tid + r * 256] = ((const float4*)Wm)[tid + r * 256];
        __syncthreads();

        int c = tid & 63, wb = tid >> 6;
        float acc[16];
        #pragma unroll
        for (int i = 0; i < 16; i++) acc[i] = 0.f;
        for (int j = 0; j < 64; j++) {
            float wv = ws[j * 64 + c];
            #pragma unroll
            for (int i = 0; i < 16; i++)
                acc[i] += xs[(wb * 16 + i) * 65 + j] * wv;
        }
        float bb = bm[c];
        #pragma unroll
        for (int i = 0; i < 16; i++)
            og[((size_t)b * 4096 + h * 64 + wb * 16 + i) * 64 + c] =
                __float2bfloat16((acc[i] + bb) * qs);
        __syncthreads();
    }

    // ---- V: transposed [b][d][t] bf16; thread = (w, cb) --------------------
    for (int r = 0; r < 4; r++)
        ((float4*)ws)[tid + r * 256] = ((const float4*)Wv)[tid + r * 256];
    __syncthreads();
    {
        int w = tid & 63, cb = tid >> 6;
        float acc[16];
        #pragma unroll
        for (int c = 0; c < 16; c++) acc[c] = 0.f;
        for (int j = 0; j < 64; j++) {
            float xv = xs[w * 65 + j];
            const float* wr = ws + j * 64 + cb * 16;
            #pragma unroll
            for (int c = 0; c < 16; c++) acc[c] += xv * wr[c];
        }
        #pragma unroll
        for (int c = 0; c < 16; c++) {
            int cc = cb * 16 + c;
            g_vtb[(size_t)(b * 64 + cc) * 4096 + h * 64 + w] =
                __float2bfloat16(acc[c] + bv[cc]);
        }
    }

    // ---- block 0 additionally emits Wo^T bf16 ------------------------------
    if (blk == 0) {
        for (int i = tid; i < 4096; i += 256) {
            int o = i & 63, in = i >> 6;
            g_woT[o * 64 + in] = __float2bfloat16(Wo[in * 64 + o]);
        }
    }
}

// ---------------- kernel 2: split-K flash attention -------------------------
// 512 threads = 16 warps. Warp-group A (warps 0-7): key tiles 0-31;
// group B (warps 8-15): tiles 32-63. Private 3-stage cp.async pipelines,
// per-group named barriers. Fixed-max log2 softmax => partials combine by
// simple addition at the end.
#define SSTR 72                    // smem row stride in bf16 (144B)
#define TILEE (64 * SSTR)          // bf16 elements per tile array

__global__ void __launch_bounds__(512, 1) attn_kernel(
    const float* __restrict__ bo, float* __restrict__ out)
{
    extern __shared__ __align__(16) __nv_bfloat16 dsm[];
    __nv_bfloat16* Qs = dsm;                        // 128 x SSTR (later: WoT)
    __nv_bfloat16* Kv = Qs + 128 * SSTR;            // [grp]{K:3 stages, V:3 stages}

    int b = blockIdx.x >> 5, qt = blockIdx.x & 31;
    int t0 = qt * 128;
    int tid = threadIdx.x;
    int warp = tid >> 5, lane = tid & 31;
    int grp = warp >> 3, warpg = warp & 7;
    int tidg = tid & 255;
    int qr = warpg * 16;
    int g = lane >> 2, c4 = lane & 3;
    int kt0 = grp * 32;

    const __nv_bfloat16* qg  = g_qb  + ((size_t)b * 4096 + t0) * 64;
    const __nv_bfloat16* kgb = g_kb  + (size_t)b * 4096 * 64;
    const __nv_bfloat16* vtg = g_vtb + (size_t)b * 64 * 4096;

    __nv_bfloat16* Kg = Kv + grp * 6 * TILEE;
    __nv_bfloat16* Vg = Kg + 3 * TILEE;

    unsigned qbase  = (unsigned)__cvta_generic_to_shared(Qs);
    unsigned kgbase = (unsigned)__cvta_generic_to_shared(Kg);
    unsigned vgbase = (unsigned)__cvta_generic_to_shared(Vg);

    int lrow0 = tidg >> 3,          lcc0 = tidg & 7;
    int lrow1 = (tidg + 256) >> 3,  lcc1 = tidg & 7;

    // ---- prologue: Q (all threads) + tiles kt0, kt0+1 (per group) ----------
    for (int i = tid; i < 1024; i += 512) {
        int row = i >> 3, cc = i & 7;
        CP_ASYNC16(qbase + (unsigned)((row * SSTR + cc * 8) * 2),
                   qg + row * 64 + cc * 8);
    }
    {
        const __nv_bfloat16* kg = kgb + (size_t)kt0 * 64 * 64;
        const __nv_bfloat16* vg = vtg + (size_t)kt0 * 64;
        CP_ASYNC16(kgbase + (unsigned)((lrow0 * SSTR + lcc0 * 8) * 2), kg + lrow0 * 64 + lcc0 * 8);
        CP_ASYNC16(kgbase + (unsigned)((lrow1 * SSTR + lcc1 * 8) * 2), kg + lrow1 * 64 + lcc1 * 8);
        CP_ASYNC16(vgbase + (unsigned)((lrow0 * SSTR + lcc0 * 8) * 2), vg + (size_t)lrow0 * 4096 + lcc0 * 8);
        CP_ASYNC16(vgbase + (unsigned)((lrow1 * SSTR + lcc1 * 8) * 2), vg + (size_t)lrow1 * 4096 + lcc1 * 8);
    }
    CP_COMMIT();   // G0: Q + tile kt0
    {
        const __nv_bfloat16* kg = kgb + (size_t)(kt0 + 1) * 64 * 64;
        const __nv_bfloat16* vg = vtg + (size_t)(kt0 + 1) * 64;
        unsigned kd = kgbase + TILEE * 2, vd = vgbase + TILEE * 2;
        CP_ASYNC16(kd + (unsigned)((lrow0 * SSTR + lcc0 * 8) * 2), kg + lrow0 * 64 + lcc0 * 8);
        CP_ASYNC16(kd + (unsigned)((lrow1 * SSTR + lcc1 * 8) * 2), kg + lrow1 * 64 + lcc1 * 8);
        CP_ASYNC16(vd + (unsigned)((lrow0 * SSTR + lcc0 * 8) * 2), vg + (size_t)lrow0 * 4096 + lcc0 * 8);
        CP_ASYNC16(vd + (unsigned)((lrow1 * SSTR + lcc1 * 8) * 2), vg + (size_t)lrow1 * 4096 + lcc1 * 8);
    }
    CP_COMMIT();   // G1: tile kt0+1

    CP_WAIT1();    // Q + tile kt0 resident (per-thread)
    __syncthreads();

    int arow = (lane & 7) + (lane & 8);
    int acol = (lane >> 4) << 3;
    unsigned aaddr = qbase + (unsigned)(((qr + arow) * SSTR + acol) * 2);
    unsigned aQ[4][4];
    #pragma unroll
    for (int kk = 0; kk < 4; kk++)
        LDSM4(aQ[kk][0], aQ[kk][1], aQ[kk][2], aQ[kk][3], aaddr + kk * 32);

    unsigned boff = (unsigned)((((lane & 7) + ((lane & 16) >> 1)) * SSTR + (lane & 8)) * 2);

    float of[8][4];
    #pragma unroll
    for (int nn = 0; nn < 8; nn++)
        #pragma unroll
        for (int i = 0; i < 4; i++) of[nn][i] = 0.f;
    float l0 = 0.f, l1 = 0.f;

    int stc = 0;
    for (int it = 0; it < 32; it++) {
        CP_WAIT1();          // tile kt0+it resident
        GROUP_BAR(grp + 1);  // group-wide: visible + prev compute done

        if (it + 2 < 32) {
            int sp = stc + 2; if (sp >= 3) sp -= 3;
            const __nv_bfloat16* kg = kgb + (size_t)(kt0 + it + 2) * 64 * 64;
            const __nv_bfloat16* vg = vtg + (size_t)(kt0 + it + 2) * 64;
            unsigned kd = kgbase + (unsigned)(sp * TILEE * 2);
            unsigned vd = vgbase + (unsigned)(sp * TILEE * 2);
            CP_ASYNC16(kd + (unsigned)((lrow0 * SSTR + lcc0 * 8) * 2), kg + lrow0 * 64 + lcc0 * 8);
            CP_ASYNC16(kd + (unsigned)((lrow1 * SSTR + lcc1 * 8) * 2), kg + lrow1 * 64 + lcc1 * 8);
            CP_ASYNC16(vd + (unsigned)((lrow0 * SSTR + lcc0 * 8) * 2), vg + (size_t)lrow0 * 4096 + lcc0 * 8);
            CP_ASYNC16(vd + (unsigned)((lrow1 * SSTR + lcc1 * 8) * 2), vg + (size_t)lrow1 * 4096 + lcc1 * 8);
        }
        CP_COMMIT();

        unsigned kb = kgbase + (unsigned)(stc * TILEE * 2) + boff;
        unsigned vb = vgbase + (unsigned)(stc * TILEE * 2) + boff;
        stc = (stc == 2) ? 0 : stc + 1;

        // ---- S = Q K^T (log2 domain, Q pre-scaled) ----
        float s[8][4];
        #pragma unroll
        for (int nn = 0; nn < 8; nn++)
            #pragma unroll
            for (int i = 0; i < 4; i++) s[nn][i] = 0.f;
        #pragma unroll
        for (int kk = 0; kk < 4; kk++) {
            #pragma unroll
            for (int np = 0; np < 4; np++) {
                unsigned b0, b1, b2, b3;
                LDSM4(b0, b1, b2, b3, kb + (unsigned)((np * 16 * SSTR + kk * 16) * 2));
                MMA16816(s[2 * np],     aQ[kk][0], aQ[kk][1], aQ[kk][2], aQ[kk][3], b0, b1);
                MMA16816(s[2 * np + 1], aQ[kk][0], aQ[kk][1], aQ[kk][2], aQ[kk][3], b2, b3);
            }
        }

        // ---- fixed-max softmax: p = 2^s ----
        #pragma unroll
        for (int nn = 0; nn < 8; nn++) {
            s[nn][0] = ex2(s[nn][0]);
            s[nn][1] = ex2(s[nn][1]);
            s[nn][2] = ex2(s[nn][2]);
            s[nn][3] = ex2(s[nn][3]);
            l0 += s[nn][0] + s[nn][1];
            l1 += s[nn][2] + s[nn][3];
        }

        // ---- O += P V ----
        #pragma unroll
        for (int kk = 0; kk < 4; kk++) {
            unsigned a0 = pk2(s[2 * kk][1],     s[2 * kk][0]);
            unsigned a1 = pk2(s[2 * kk][3],     s[2 * kk][2]);
            unsigned a2 = pk2(s[2 * kk + 1][1], s[2 * kk + 1][0]);
            unsigned a3 = pk2(s[2 * kk + 1][3], s[2 * kk + 1][2]);
            #pragma unroll
            for (int np = 0; np < 4; np++) {
                unsigned b0, b1, b2, b3;
                LDSM4(b0, b1, b2, b3, vb + (unsigned)((np * 16 * SSTR + kk * 16) * 2));
                MMA16816(of[2 * np],     a0, a1, a2, a3, b0, b1);
                MMA16816(of[2 * np + 1], a0, a1, a2, a3, b2, b3);
            }
        }
    }

    // ---- combine split-K partials (exchange via group-B smem area) ---------
    __syncthreads();
    float* ex = (float*)(Kv + 6 * TILEE);   // 256 lanes x 35 floats = 35840 B
    if (grp == 1) {
        float* pp = ex + (warpg * 32 + lane) * 35;
        #pragma unroll
        for (int nn = 0; nn < 8; nn++)
            #pragma unroll
            for (int i = 0; i < 4; i++) pp[nn * 4 + i] = of[nn][i];
        pp[32] = l0; pp[33] = l1;
    }
    __syncthreads();
    if (grp == 1) return;

    {
        float* pp = ex + (warpg * 32 + lane) * 35;
        #pragma unroll
        for (int nn = 0; nn < 8; nn++)
            #pragma unroll
            for (int i = 0; i < 4; i++) of[nn][i] += pp[nn * 4 + i];
        l0 += pp[32]; l1 += pp[33];
    }
    l0 += __shfl_xor_sync(0xffffffffu, l0, 1);
    l0 += __shfl_xor_sync(0xffffffffu, l0, 2);
    l1 += __shfl_xor_sync(0xffffffffu, l1, 1);
    l1 += __shfl_xor_sync(0xffffffffu, l1, 2);

    // ---- epilogue (group A only): res = (O/l) @ Wo + bo + xn ---------------
    for (int i = tidg; i < 512; i += 256) {
        int row = i >> 3, cc = i & 7;
        *(float4*)(Qs + row * SSTR + cc * 8) =
            *(const float4*)(g_woT + row * 64 + cc * 8);
    }
    GROUP_BAR(1);

    float inv0 = 1.f / l0, inv1 = 1.f / l1;
    #pragma unroll
    for (int nn = 0; nn < 8; nn++) {
        of[nn][0] *= inv0; of[nn][1] *= inv0;
        of[nn][2] *= inv1; of[nn][3] *= inv1;
    }

    float r[8][4];
    #pragma unroll
    for (int nn = 0; nn < 8; nn++)
        #pragma unroll
        for (int i = 0; i < 4; i++) r[nn][i] = 0.f;
    #pragma unroll
    for (int kk = 0; kk < 4; kk++) {
        unsigned a0 = pk2(of[2 * kk][1],     of[2 * kk][0]);
        unsigned a1 = pk2(of[2 * kk][3],     of[2 * kk][2]);
        unsigned a2 = pk2(of[2 * kk + 1][1], of[2 * kk + 1][0]);
        unsigned a3 = pk2(of[2 * kk + 1][3], of[2 * kk + 1][2]);
        #pragma unroll
        for (int np = 0; np < 4; np++) {
            unsigned b0, b1, b2, b3;
            LDSM4(b0, b1, b2, b3, qbase + boff + (unsigned)((np * 16 * SSTR + kk * 16) * 2));
            MMA16816(r[2 * np],     a0, a1, a2, a3, b0, b1);
            MMA16816(r[2 * np + 1], a0, a1, a2, a3, b2, b3);
        }
    }

    #pragma unroll
    for (int nn = 0; nn < 8; nn++) {
        int col = nn * 8 + c4 * 2;
        float2 bv = *(const float2*)(bo + col);
        size_t i0 = ((size_t)b * 4096 + t0 + qr + g) * 64 + col;
        float2 x0 = *(const float2*)(g_xn + i0);
        float2 o0 = make_float2(r[nn][0] + bv.x + x0.x, r[nn][1] + bv.y + x0.y);
        *(float2*)(out + i0) = o0;
        size_t i1 = i0 + (size_t)8 * 64;
        float2 x1 = *(const float2*)(g_xn + i1);
        float2 o1 = make_float2(r[nn][2] + bv.x + x1.x, r[nn][3] + bv.y + x1.y);
        *(float2*)(out + i1) = o1;
    }
}

// ---------------- launch ----------------------------------------------------
extern "C" void kernel_launch(void* const* d_in, const int* in_sizes, int n_in,
                              void* d_out, int out_size)
{
    const float* x     = (const float*)d_in[0];
    const float* gamma = (const float*)d_in[1];
    const float* beta  = (const float*)d_in[2];
    const float* Wq    = (const float*)d_in[3];
    const float* bq    = (const float*)d_in[4];
    const float* Wk    = (const float*)d_in[5];
    const float* bk    = (const float*)d_in[6];
    const float* Wv    = (const float*)d_in[7];
    const float* bv    = (const float*)d_in[8];
    const float* Wo    = (const float*)d_in[9];
    const float* bo    = (const float*)d_in[10];
    float* out = (float*)d_out;

    const int attn_smem = (128 * SSTR + 12 * 64 * SSTR) * 2;   // 129024 B
    cudaFuncSetAttribute(attn_kernel,
                         cudaFuncAttributeMaxDynamicSharedMemorySize, attn_smem);

    gn_qkv_kernel<<<BATCH * 64, 256>>>(x, gamma, beta, Wq, bq, Wk, bk, Wv, bv, Wo);
    attn_kernel<<<BATCH * 32, 512, attn_smem>>>(bo, out);
}